// round 1
// baseline (speedup 1.0000x reference)
#include <cuda_runtime.h>
#include <cstdint>

// Problem constants (fixed by setup_inputs)
#define B_  2
#define S_  2048
#define D_  1024
#define H_  16
#define HD_ 64
#define M_  (B_ * S_)   // 4096

// ---------------------------------------------------------------------------
// Scratch (no allocation allowed -> __device__ globals). 4 x 16 MB = 64 MB.
// ---------------------------------------------------------------------------
__device__ float g_q[(size_t)M_ * D_];
__device__ float g_k[(size_t)M_ * D_];
__device__ float g_v[(size_t)M_ * D_];
__device__ float g_attn[(size_t)M_ * D_];

// ---------------------------------------------------------------------------
// Packed f32x2 helpers (sm_100+): 2 FMAs per issue slot on the fma pipe.
// ---------------------------------------------------------------------------
__device__ __forceinline__ unsigned long long pack2f(float lo, float hi) {
    unsigned long long r;
    asm("mov.b64 %0, {%1, %2};" : "=l"(r) : "f"(lo), "f"(hi));
    return r;
}
__device__ __forceinline__ void unpack2f(unsigned long long p, float &lo, float &hi) {
    asm("mov.b64 {%0, %1}, %2;" : "=f"(lo), "=f"(hi) : "l"(p));
}
__device__ __forceinline__ void fma2(unsigned long long &d,
                                     unsigned long long a,
                                     unsigned long long b) {
    asm("fma.rn.f32x2 %0, %1, %2, %0;" : "+l"(d) : "l"(a), "l"(b));
}

// ---------------------------------------------------------------------------
// GEMM: C[M,N] = A[M,K] @ Bw[N,K]^T   (both operands K-major row-major)
// Block 128x128, BK=16, 256 threads, 8x8 per thread (as 8x4 f32x2 pairs).
// ---------------------------------------------------------------------------
__global__ __launch_bounds__(256) void gemm_nt_kernel(
    const float* __restrict__ A, const float* __restrict__ Bw,
    float* __restrict__ C, int M, int N, int K)
{
    __shared__ float As[16][128];   // [k][m]
    __shared__ float Bs[16][128];   // [k][n]

    const int tid = threadIdx.x;
    const int tx  = tid & 15;       // n-frag index
    const int ty  = tid >> 4;       // m-frag index
    const int m0  = blockIdx.y * 128;
    const int n0  = blockIdx.x * 128;

    unsigned long long acc[8][4];
#pragma unroll
    for (int i = 0; i < 8; i++)
#pragma unroll
        for (int j = 0; j < 4; j++) acc[i][j] = 0ULL;

    for (int k0 = 0; k0 < K; k0 += 16) {
#pragma unroll
        for (int t = 0; t < 2; t++) {
            int idx = tid + t * 256;     // 0..511
            int row = idx >> 2;          // 0..127
            int k4  = idx & 3;           // 0..3 (float4 per 16-wide k slab)
            float4 a = *(const float4*)(A + (size_t)(m0 + row) * K + k0 + k4 * 4);
            As[k4 * 4 + 0][row] = a.x; As[k4 * 4 + 1][row] = a.y;
            As[k4 * 4 + 2][row] = a.z; As[k4 * 4 + 3][row] = a.w;
            float4 b = *(const float4*)(Bw + (size_t)(n0 + row) * K + k0 + k4 * 4);
            Bs[k4 * 4 + 0][row] = b.x; Bs[k4 * 4 + 1][row] = b.y;
            Bs[k4 * 4 + 2][row] = b.z; Bs[k4 * 4 + 3][row] = b.w;
        }
        __syncthreads();

#pragma unroll
        for (int kk = 0; kk < 16; kk++) {
            float4 a0 = *(const float4*)&As[kk][ty * 8];
            float4 a1 = *(const float4*)&As[kk][ty * 8 + 4];
            float4 b0 = *(const float4*)&Bs[kk][tx * 8];
            float4 b1 = *(const float4*)&Bs[kk][tx * 8 + 4];
            unsigned long long pb[4] = {
                pack2f(b0.x, b0.y), pack2f(b0.z, b0.w),
                pack2f(b1.x, b1.y), pack2f(b1.z, b1.w)
            };
            float av[8] = {a0.x, a0.y, a0.z, a0.w, a1.x, a1.y, a1.z, a1.w};
#pragma unroll
            for (int i = 0; i < 8; i++) {
                unsigned long long pa = pack2f(av[i], av[i]);
#pragma unroll
                for (int j = 0; j < 4; j++) fma2(acc[i][j], pa, pb[j]);
            }
        }
        __syncthreads();
    }

#pragma unroll
    for (int i = 0; i < 8; i++) {
        float out[8];
#pragma unroll
        for (int j = 0; j < 4; j++) unpack2f(acc[i][j], out[2 * j], out[2 * j + 1]);
        float4* dst = (float4*)(C + (size_t)(m0 + ty * 8 + i) * N + n0 + tx * 8);
        dst[0] = make_float4(out[0], out[1], out[2], out[3]);
        dst[1] = make_float4(out[4], out[5], out[6], out[7]);
    }
}

// ---------------------------------------------------------------------------
// RoPE, in-place on q and k (row-major [B*S, D], heads = 16 chunks of 64).
// Pair (2j, 2j+1) within each head rotated by (cos,sin)[s][j], j in [0,32).
// ---------------------------------------------------------------------------
__global__ void rope_kernel(float2* __restrict__ q, float2* __restrict__ k,
                            const float* __restrict__ fc,
                            const float* __restrict__ fs)
{
    int p = blockIdx.x * blockDim.x + threadIdx.x;   // pair index, [0, M_*D_/2)
    int c   = p & 511;          // pair-in-row (D/2 = 512)
    int row = p >> 9;           // b*S + s
    int s   = row & (S_ - 1);
    int j   = c & 31;           // pair-in-head (hd/2 = 32)
    float cv = fc[s * 32 + j];
    float sv = fs[s * 32 + j];
    float2 qv = q[p];
    q[p] = make_float2(qv.x * cv - qv.y * sv, qv.y * cv + qv.x * sv);
    float2 kv = k[p];
    k[p] = make_float2(kv.x * cv - kv.y * sv, kv.y * cv + kv.x * sv);
}

// ---------------------------------------------------------------------------
// Causal flash attention, fp32. One block per (q_tile, b*h).
// 64x64 tiles, 256 threads = 16x16, 4x4 fragments.
// smem: Qt [d][q] 16KB, KtPs (Kt [d][k], then aliased as P [q][k]) 16KB,
//       Vs [k][d] 16KB  -> exactly 48 KB static.
// ---------------------------------------------------------------------------
__global__ __launch_bounds__(256) void attn_kernel(
    const float* __restrict__ q, const float* __restrict__ k,
    const float* __restrict__ v, float* __restrict__ o)
{
    __shared__ float Qt[64 * 64];
    __shared__ float KtPs[64 * 64];
    __shared__ float Vs[64 * 64];

    const int qt = 31 - blockIdx.x;          // heavy blocks first
    const int bh = blockIdx.y;
    const int b  = bh >> 4;
    const int h  = bh & 15;
    const int tid = threadIdx.x;
    const int tx  = tid & 15;
    const int ty  = tid >> 4;
    const size_t base = ((size_t)b * S_) * D_ + (size_t)h * HD_;

    // Load Q tile, transposed to [d][q]
#pragma unroll
    for (int t = 0; t < 4; t++) {
        int idx = tid + t * 256;             // 0..1023
        int row = idx >> 4;                  // 0..63
        int c4  = idx & 15;                  // 0..15
        float4 val = *(const float4*)(q + base + (size_t)(qt * 64 + row) * D_ + c4 * 4);
        Qt[(c4 * 4 + 0) * 64 + row] = val.x;
        Qt[(c4 * 4 + 1) * 64 + row] = val.y;
        Qt[(c4 * 4 + 2) * 64 + row] = val.z;
        Qt[(c4 * 4 + 3) * 64 + row] = val.w;
    }

    float m[4], l[4], oa[4][4];
#pragma unroll
    for (int i = 0; i < 4; i++) {
        m[i] = -1e30f; l[i] = 0.f;
#pragma unroll
        for (int j = 0; j < 4; j++) oa[i][j] = 0.f;
    }
    __syncthreads();

    for (int kt = 0; kt <= qt; kt++) {
        // Load K tile transposed [d][k], V tile natural [k][d]
#pragma unroll
        for (int t = 0; t < 4; t++) {
            int idx = tid + t * 256;
            int row = idx >> 4;
            int c4  = idx & 15;
            float4 kf = *(const float4*)(k + base + (size_t)(kt * 64 + row) * D_ + c4 * 4);
            KtPs[(c4 * 4 + 0) * 64 + row] = kf.x;
            KtPs[(c4 * 4 + 1) * 64 + row] = kf.y;
            KtPs[(c4 * 4 + 2) * 64 + row] = kf.z;
            KtPs[(c4 * 4 + 3) * 64 + row] = kf.w;
            float4 vf = *(const float4*)(v + base + (size_t)(kt * 64 + row) * D_ + c4 * 4);
            *(float4*)&Vs[row * 64 + c4 * 4] = vf;
        }
        __syncthreads();

        // S = Q K^T  (4x4 fragment per thread)
        float s[4][4];
#pragma unroll
        for (int i = 0; i < 4; i++)
#pragma unroll
            for (int j = 0; j < 4; j++) s[i][j] = 0.f;

#pragma unroll 16
        for (int d = 0; d < 64; d++) {
            float4 qf = *(const float4*)&Qt[d * 64 + ty * 4];
            float4 kf = *(const float4*)&KtPs[d * 64 + tx * 4];
            float qa[4] = {qf.x, qf.y, qf.z, qf.w};
            float ka[4] = {kf.x, kf.y, kf.z, kf.w};
#pragma unroll
            for (int i = 0; i < 4; i++)
#pragma unroll
                for (int j = 0; j < 4; j++) s[i][j] += qa[i] * ka[j];
        }

        // scale + causal mask + online softmax (row group = 16 tx lanes)
        const bool diag = (kt == qt);
#pragma unroll
        for (int i = 0; i < 4; i++) {
            float mt = -1e30f;
#pragma unroll
            for (int j = 0; j < 4; j++) {
                s[i][j] *= 0.125f;   // 1/sqrt(64)
                if (diag && (tx * 4 + j) > (ty * 4 + i)) s[i][j] = -1e30f;
                mt = fmaxf(mt, s[i][j]);
            }
#pragma unroll
            for (int off = 8; off; off >>= 1)
                mt = fmaxf(mt, __shfl_xor_sync(0xffffffffu, mt, off));
            float mn = fmaxf(m[i], mt);
            float sc = __expf(m[i] - mn);
            m[i] = mn;
            float rs = 0.f;
#pragma unroll
            for (int j = 0; j < 4; j++) {
                s[i][j] = __expf(s[i][j] - mn);
                rs += s[i][j];
            }
#pragma unroll
            for (int off = 8; off; off >>= 1)
                rs += __shfl_xor_sync(0xffffffffu, rs, off);
            l[i] = l[i] * sc + rs;
#pragma unroll
            for (int j = 0; j < 4; j++) oa[i][j] *= sc;
        }

        __syncthreads();   // all Kt reads done -> safe to alias with P
#pragma unroll
        for (int i = 0; i < 4; i++)
            *(float4*)&KtPs[(ty * 4 + i) * 64 + tx * 4] =
                make_float4(s[i][0], s[i][1], s[i][2], s[i][3]);
        __syncthreads();

        // O += P V
#pragma unroll 8
        for (int kk = 0; kk < 64; kk++) {
            float4 vf = *(const float4*)&Vs[kk * 64 + tx * 4];
            float va[4] = {vf.x, vf.y, vf.z, vf.w};
#pragma unroll
            for (int i = 0; i < 4; i++) {
                float pv = KtPs[(ty * 4 + i) * 64 + kk];
#pragma unroll
                for (int j = 0; j < 4; j++) oa[i][j] += pv * va[j];
            }
        }
        __syncthreads();   // before next tile overwrites KtPs / Vs
    }

    // Normalize and write attn output directly in [B,S,D] = attn_cat layout
#pragma unroll
    for (int i = 0; i < 4; i++) {
        float inv = 1.0f / l[i];
        float4 r = make_float4(oa[i][0] * inv, oa[i][1] * inv,
                               oa[i][2] * inv, oa[i][3] * inv);
        *(float4*)(o + base + (size_t)(qt * 64 + ty * 4 + i) * D_ + tx * 4) = r;
    }
}

// ---------------------------------------------------------------------------
// kernel_launch: x, freqs_cos, freqs_sin, Wq, Wk, Wv, Wo  ->  out [B,S,D] f32
// ---------------------------------------------------------------------------
extern "C" void kernel_launch(void* const* d_in, const int* in_sizes, int n_in,
                              void* d_out, int out_size)
{
    (void)in_sizes; (void)n_in; (void)out_size;
    const float* x  = (const float*)d_in[0];
    const float* fc = (const float*)d_in[1];
    const float* fs = (const float*)d_in[2];
    const float* Wq = (const float*)d_in[3];
    const float* Wk = (const float*)d_in[4];
    const float* Wv = (const float*)d_in[5];
    const float* Wo = (const float*)d_in[6];
    float* out = (float*)d_out;

    float *qb, *kb, *vb, *ab;
    cudaGetSymbolAddress((void**)&qb, g_q);
    cudaGetSymbolAddress((void**)&kb, g_k);
    cudaGetSymbolAddress((void**)&vb, g_v);
    cudaGetSymbolAddress((void**)&ab, g_attn);

    dim3 gg(D_ / 128, M_ / 128);   // (8, 32)
    gemm_nt_kernel<<<gg, 256>>>(x, Wq, qb, M_, D_, D_);
    gemm_nt_kernel<<<gg, 256>>>(x, Wk, kb, M_, D_, D_);
    gemm_nt_kernel<<<gg, 256>>>(x, Wv, vb, M_, D_, D_);

    rope_kernel<<<(M_ * D_ / 2) / 256, 256>>>((float2*)qb, (float2*)kb, fc, fs);

    attn_kernel<<<dim3(32, 32), 256>>>(qb, kb, vb, ab);

    gemm_nt_kernel<<<gg, 256>>>(ab, Wo, out, M_, D_, D_);
}

// round 3
// speedup vs baseline: 1.5830x; 1.5830x over previous
#include <cuda_runtime.h>
#include <cuda_bf16.h>
#include <cstdint>

// Problem constants (fixed by setup_inputs)
#define B_  2
#define S_  2048
#define D_  1024
#define H_  16
#define HD_ 64
#define M_  (B_ * S_)     // 4096
#define KCAT 3072         // 3x hi/lo split K

// ---------------------------------------------------------------------------
// Scratch (__device__ globals; no allocation allowed)
// ---------------------------------------------------------------------------
__device__ float g_q[(size_t)M_ * D_];
__device__ float g_k[(size_t)M_ * D_];
__device__ float g_v[(size_t)M_ * D_];
__device__ float g_attn[(size_t)M_ * D_];
__device__ __nv_bfloat16 g_xcat[(size_t)M_ * KCAT];        // [x_hi | x_lo | x_hi]
__device__ __nv_bfloat16 g_wcat[4][(size_t)D_ * KCAT];     // [W_hi | W_hi | W_lo]
__device__ __nv_bfloat16 g_acat[(size_t)M_ * KCAT];

// ---------------------------------------------------------------------------
// Helpers
// ---------------------------------------------------------------------------
__device__ __forceinline__ uint32_t smem_u32(const void* p) {
    uint32_t a;
    asm("{ .reg .u64 t; cvta.to.shared.u64 t, %1; cvt.u32.u64 %0, t; }"
        : "=r"(a) : "l"(p));
    return a;
}
__device__ __forceinline__ uint32_t sw128(uint32_t o) { return o ^ ((o >> 3) & 0x70); }

#define CP_ASYNC16(saddr, gptr) \
    asm volatile("cp.async.cg.shared.global [%0], [%1], 16;" \
                 :: "r"(saddr), "l"(gptr) : "memory")
#define CP_COMMIT() asm volatile("cp.async.commit_group;" ::: "memory")
#define CP_WAIT1()  asm volatile("cp.async.wait_group 1;" ::: "memory")
#define CP_WAIT0()  asm volatile("cp.async.wait_group 0;" ::: "memory")

#define LDMATRIX_X4(r0, r1, r2, r3, addr) \
    asm volatile("ldmatrix.sync.aligned.m8n8.x4.shared.b16 {%0,%1,%2,%3}, [%4];" \
                 : "=r"(r0), "=r"(r1), "=r"(r2), "=r"(r3) : "r"(addr))

#define MMA_BF16(d, a, b) \
    asm volatile("mma.sync.aligned.m16n8k16.row.col.f32.bf16.bf16.f32 " \
                 "{%0,%1,%2,%3}, {%4,%5,%6,%7}, {%8,%9}, {%0,%1,%2,%3};" \
                 : "+f"((d)[0]), "+f"((d)[1]), "+f"((d)[2]), "+f"((d)[3]) \
                 : "r"((a)[0]), "r"((a)[1]), "r"((a)[2]), "r"((a)[3]),   \
                   "r"((b)[0]), "r"((b)[1]))

// ---------------------------------------------------------------------------
// Split kernel: src fp32 [rows, 1024] -> dst bf16 [rows, 3072]
// aMode=1: [hi | lo | hi]   (activations);  aMode=0: [hi | hi | lo]  (weights)
// ---------------------------------------------------------------------------
__global__ void split_kernel(const float2* __restrict__ src,
                             __nv_bfloat162* __restrict__ dst,
                             int rows, int aMode)
{
    int p = blockIdx.x * blockDim.x + threadIdx.x;
    if (p >= rows * 512) return;
    int row = p >> 9;
    int cp  = p & 511;
    float2 v = src[p];
    __nv_bfloat16 h0 = __float2bfloat16(v.x);
    __nv_bfloat16 h1 = __float2bfloat16(v.y);
    __nv_bfloat16 l0 = __float2bfloat16(v.x - __bfloat162float(h0));
    __nv_bfloat16 l1 = __float2bfloat16(v.y - __bfloat162float(h1));
    __nv_bfloat162 hi; hi.x = h0; hi.y = h1;
    __nv_bfloat162 lo; lo.x = l0; lo.y = l1;
    __nv_bfloat162* drow = dst + (size_t)row * 1536;
    drow[cp]        = hi;
    drow[512 + cp]  = aMode ? lo : hi;
    drow[1024 + cp] = aMode ? hi : lo;
}

// ---------------------------------------------------------------------------
// HMMA bf16 GEMM: C[M,1024] = Acat[M,3072] @ Bcat[1024,3072]^T, fp32 out.
// CTA 128x128, BK=64, 8 warps (2x4 -> 64x32 warp tiles), cp.async double buf.
// Smem tile layout: 128 rows x 128 bytes, XOR-swizzled within the row.
// ---------------------------------------------------------------------------
#define STAGE_BYTES 32768                 // 16 KB A + 16 KB B
#define GEMM_SMEM   (2 * STAGE_BYTES)     // 64 KB
#define NCHUNK      (KCAT / 64)           // 48

__global__ __launch_bounds__(256) void gemm_tc_kernel(
    const __nv_bfloat16* __restrict__ A,
    const __nv_bfloat16* __restrict__ Bw,
    float* __restrict__ C)
{
    extern __shared__ char dyn[];
    const int tid  = threadIdx.x;
    const int wid  = tid >> 5;
    const int lane = tid & 31;
    const int wm   = wid >> 2;            // 0..1
    const int wn   = wid & 3;             // 0..3
    const int m0   = blockIdx.y * 128;
    const int n0   = blockIdx.x * 128;
    const uint32_t smem = smem_u32(dyn);

    // per-thread load coords: 256 threads x (4 rows each) cover 128 rows x 128B
    const int lrow = tid >> 3;            // 0..31
    const int lc16 = tid & 7;             // 16B chunk in row
    const __nv_bfloat16* gA = A  + (size_t)(m0 + lrow) * KCAT + lc16 * 8;
    const __nv_bfloat16* gB = Bw + (size_t)(n0 + lrow) * KCAT + lc16 * 8;
    const uint32_t sA0 = smem + sw128(lrow * 128 + lc16 * 16);          // +j*4096
    const uint32_t sB0 = sA0 + 16384;

#define PREFETCH(c, stg) do {                                                   \
    const __nv_bfloat16* pa = gA + (size_t)(c) * 64;                            \
    const __nv_bfloat16* pb = gB + (size_t)(c) * 64;                            \
    uint32_t off = (stg) * STAGE_BYTES;                                         \
    _Pragma("unroll")                                                           \
    for (int j = 0; j < 4; j++) {                                               \
        CP_ASYNC16(sA0 + off + j * 4096, pa + (size_t)j * 32 * KCAT);           \
        CP_ASYNC16(sB0 + off + j * 4096, pb + (size_t)j * 32 * KCAT);           \
    }                                                                           \
    CP_COMMIT(); } while (0)

    float acc[4][4][4];
#pragma unroll
    for (int i = 0; i < 4; i++)
#pragma unroll
        for (int j = 0; j < 4; j++)
#pragma unroll
            for (int q = 0; q < 4; q++) acc[i][j][q] = 0.f;

    // ldmatrix per-lane geometry (constant across k-steps except col byte)
    const int arow = wm * 64 + (lane & 15);            // + mf*16
    const int acb0 = (lane >> 4) * 16;                 // 0 or 16
    const int brow = wn * 32 + (lane & 7) + ((lane >> 4) << 3);   // + nf2*16
    const int bcb0 = ((lane >> 3) & 1) * 16;

    PREFETCH(0, 0);

    for (int c = 0; c < NCHUNK; c++) {
        const int s = c & 1;
        const bool has_next = (c + 1 < NCHUNK);
        if (has_next) { PREFETCH(c + 1, s ^ 1); CP_WAIT1(); }
        else          { CP_WAIT0(); }
        __syncthreads();

        const uint32_t abase = smem + s * STAGE_BYTES;
        const uint32_t bbase = abase + 16384;

#pragma unroll
        for (int ks = 0; ks < 4; ks++) {
            uint32_t a[4][4], b[4][2];
#pragma unroll
            for (int mf = 0; mf < 4; mf++) {
                int row = arow + mf * 16;
                int cb  = ks * 32 + acb0;
                uint32_t addr = abase + row * 128 + (cb ^ ((row & 7) << 4));
                LDMATRIX_X4(a[mf][0], a[mf][1], a[mf][2], a[mf][3], addr);
            }
#pragma unroll
            for (int nf2 = 0; nf2 < 2; nf2++) {
                int row = brow + nf2 * 16;
                int cb  = ks * 32 + bcb0;
                uint32_t addr = bbase + row * 128 + (cb ^ ((row & 7) << 4));
                uint32_t r0, r1, r2, r3;
                LDMATRIX_X4(r0, r1, r2, r3, addr);
                b[nf2 * 2][0] = r0; b[nf2 * 2][1] = r1;
                b[nf2 * 2 + 1][0] = r2; b[nf2 * 2 + 1][1] = r3;
            }
#pragma unroll
            for (int mf = 0; mf < 4; mf++)
#pragma unroll
                for (int nf = 0; nf < 4; nf++)
                    MMA_BF16(acc[mf][nf], a[mf], b[nf]);
        }
        __syncthreads();
    }
#undef PREFETCH

    // epilogue
#pragma unroll
    for (int mf = 0; mf < 4; mf++) {
        int r = m0 + wm * 64 + mf * 16 + (lane >> 2);
#pragma unroll
        for (int nf = 0; nf < 4; nf++) {
            int cN = n0 + wn * 32 + nf * 8 + (lane & 3) * 2;
            *(float2*)(C + (size_t)r * D_ + cN) =
                make_float2(acc[mf][nf][0], acc[mf][nf][1]);
            *(float2*)(C + (size_t)(r + 8) * D_ + cN) =
                make_float2(acc[mf][nf][2], acc[mf][nf][3]);
        }
    }
}

// ---------------------------------------------------------------------------
// RoPE, in-place on q and k
// ---------------------------------------------------------------------------
__global__ void rope_kernel(float2* __restrict__ q, float2* __restrict__ k,
                            const float* __restrict__ fc,
                            const float* __restrict__ fs)
{
    int p = blockIdx.x * blockDim.x + threadIdx.x;
    int c   = p & 511;
    int row = p >> 9;
    int s   = row & (S_ - 1);
    int j   = c & 31;
    float cv = fc[s * 32 + j];
    float sv = fs[s * 32 + j];
    float2 qv = q[p];
    q[p] = make_float2(qv.x * cv - qv.y * sv, qv.y * cv + qv.x * sv);
    float2 kv = k[p];
    k[p] = make_float2(kv.x * cv - kv.y * sv, kv.y * cv + kv.x * sv);
}

// ---------------------------------------------------------------------------
// Causal flash attention, fp32 SIMT (unchanged; passed round 1)
// ---------------------------------------------------------------------------
__global__ __launch_bounds__(256) void attn_kernel(
    const float* __restrict__ q, const float* __restrict__ k,
    const float* __restrict__ v, float* __restrict__ o)
{
    __shared__ float Qt[64 * 64];
    __shared__ float KtPs[64 * 64];
    __shared__ float Vs[64 * 64];

    const int qt = 31 - blockIdx.x;
    const int bh = blockIdx.y;
    const int b  = bh >> 4;
    const int h  = bh & 15;
    const int tid = threadIdx.x;
    const int tx  = tid & 15;
    const int ty  = tid >> 4;
    const size_t base = ((size_t)b * S_) * D_ + (size_t)h * HD_;

#pragma unroll
    for (int t = 0; t < 4; t++) {
        int idx = tid + t * 256;
        int row = idx >> 4;
        int c4  = idx & 15;
        float4 val = *(const float4*)(q + base + (size_t)(qt * 64 + row) * D_ + c4 * 4);
        Qt[(c4 * 4 + 0) * 64 + row] = val.x;
        Qt[(c4 * 4 + 1) * 64 + row] = val.y;
        Qt[(c4 * 4 + 2) * 64 + row] = val.z;
        Qt[(c4 * 4 + 3) * 64 + row] = val.w;
    }

    float m[4], l[4], oa[4][4];
#pragma unroll
    for (int i = 0; i < 4; i++) {
        m[i] = -1e30f; l[i] = 0.f;
#pragma unroll
        for (int j = 0; j < 4; j++) oa[i][j] = 0.f;
    }
    __syncthreads();

    for (int kt = 0; kt <= qt; kt++) {
#pragma unroll
        for (int t = 0; t < 4; t++) {
            int idx = tid + t * 256;
            int row = idx >> 4;
            int c4  = idx & 15;
            float4 kf = *(const float4*)(k + base + (size_t)(kt * 64 + row) * D_ + c4 * 4);
            KtPs[(c4 * 4 + 0) * 64 + row] = kf.x;
            KtPs[(c4 * 4 + 1) * 64 + row] = kf.y;
            KtPs[(c4 * 4 + 2) * 64 + row] = kf.z;
            KtPs[(c4 * 4 + 3) * 64 + row] = kf.w;
            float4 vf = *(const float4*)(v + base + (size_t)(kt * 64 + row) * D_ + c4 * 4);
            *(float4*)&Vs[row * 64 + c4 * 4] = vf;
        }
        __syncthreads();

        float s[4][4];
#pragma unroll
        for (int i = 0; i < 4; i++)
#pragma unroll
            for (int j = 0; j < 4; j++) s[i][j] = 0.f;

#pragma unroll 16
        for (int d = 0; d < 64; d++) {
            float4 qf = *(const float4*)&Qt[d * 64 + ty * 4];
            float4 kf = *(const float4*)&KtPs[d * 64 + tx * 4];
            float qa[4] = {qf.x, qf.y, qf.z, qf.w};
            float ka[4] = {kf.x, kf.y, kf.z, kf.w};
#pragma unroll
            for (int i = 0; i < 4; i++)
#pragma unroll
                for (int j = 0; j < 4; j++) s[i][j] += qa[i] * ka[j];
        }

        const bool diag = (kt == qt);
#pragma unroll
        for (int i = 0; i < 4; i++) {
            float mt = -1e30f;
#pragma unroll
            for (int j = 0; j < 4; j++) {
                s[i][j] *= 0.125f;
                if (diag && (tx * 4 + j) > (ty * 4 + i)) s[i][j] = -1e30f;
                mt = fmaxf(mt, s[i][j]);
            }
#pragma unroll
            for (int off = 8; off; off >>= 1)
                mt = fmaxf(mt, __shfl_xor_sync(0xffffffffu, mt, off));
            float mn = fmaxf(m[i], mt);
            float sc = __expf(m[i] - mn);
            m[i] = mn;
            float rs = 0.f;
#pragma unroll
            for (int j = 0; j < 4; j++) {
                s[i][j] = __expf(s[i][j] - mn);
                rs += s[i][j];
            }
#pragma unroll
            for (int off = 8; off; off >>= 1)
                rs += __shfl_xor_sync(0xffffffffu, rs, off);
            l[i] = l[i] * sc + rs;
#pragma unroll
            for (int j = 0; j < 4; j++) oa[i][j] *= sc;
        }

        __syncthreads();
#pragma unroll
        for (int i = 0; i < 4; i++)
            *(float4*)&KtPs[(ty * 4 + i) * 64 + tx * 4] =
                make_float4(s[i][0], s[i][1], s[i][2], s[i][3]);
        __syncthreads();

#pragma unroll 8
        for (int kk = 0; kk < 64; kk++) {
            float4 vf = *(const float4*)&Vs[kk * 64 + tx * 4];
            float va[4] = {vf.x, vf.y, vf.z, vf.w};
#pragma unroll
            for (int i = 0; i < 4; i++) {
                float pv = KtPs[(ty * 4 + i) * 64 + kk];
#pragma unroll
                for (int j = 0; j < 4; j++) oa[i][j] += pv * va[j];
            }
        }
        __syncthreads();
    }

#pragma unroll
    for (int i = 0; i < 4; i++) {
        float inv = 1.0f / l[i];
        float4 r = make_float4(oa[i][0] * inv, oa[i][1] * inv,
                               oa[i][2] * inv, oa[i][3] * inv);
        *(float4*)(o + base + (size_t)(qt * 64 + ty * 4 + i) * D_ + tx * 4) = r;
    }
}

// ---------------------------------------------------------------------------
// kernel_launch
// ---------------------------------------------------------------------------
extern "C" void kernel_launch(void* const* d_in, const int* in_sizes, int n_in,
                              void* d_out, int out_size)
{
    (void)in_sizes; (void)n_in; (void)out_size;
    const float* x  = (const float*)d_in[0];
    const float* fc = (const float*)d_in[1];
    const float* fs = (const float*)d_in[2];
    const float* Ws[4] = { (const float*)d_in[3], (const float*)d_in[4],
                           (const float*)d_in[5], (const float*)d_in[6] };
    float* out = (float*)d_out;

    float *qb, *kb, *vb, *ab;
    __nv_bfloat16 *xcat, *wcat, *acat;
    cudaGetSymbolAddress((void**)&qb, g_q);
    cudaGetSymbolAddress((void**)&kb, g_k);
    cudaGetSymbolAddress((void**)&vb, g_v);
    cudaGetSymbolAddress((void**)&ab, g_attn);
    cudaGetSymbolAddress((void**)&xcat, g_xcat);
    cudaGetSymbolAddress((void**)&wcat, g_wcat);
    cudaGetSymbolAddress((void**)&acat, g_acat);

    cudaFuncSetAttribute(gemm_tc_kernel,
                         cudaFuncAttributeMaxDynamicSharedMemorySize, GEMM_SMEM);

    split_kernel<<<(M_ * 512) / 256, 256>>>((const float2*)x,
                                            (__nv_bfloat162*)xcat, M_, 1);
    for (int w = 0; w < 4; w++)
        split_kernel<<<(D_ * 512) / 256, 256>>>((const float2*)Ws[w],
            (__nv_bfloat162*)(wcat + (size_t)w * D_ * KCAT), D_, 0);

    dim3 gg(D_ / 128, M_ / 128);   // (8, 32)
    gemm_tc_kernel<<<gg, 256, GEMM_SMEM>>>(xcat, wcat + 0 * (size_t)D_ * KCAT, qb);
    gemm_tc_kernel<<<gg, 256, GEMM_SMEM>>>(xcat, wcat + 1 * (size_t)D_ * KCAT, kb);
    gemm_tc_kernel<<<gg, 256, GEMM_SMEM>>>(xcat, wcat + 2 * (size_t)D_ * KCAT, vb);

    rope_kernel<<<(M_ * D_ / 2) / 256, 256>>>((float2*)qb, (float2*)kb, fc, fs);

    attn_kernel<<<dim3(32, 32), 256>>>(qb, kb, vb, ab);

    split_kernel<<<(M_ * 512) / 256, 256>>>((const float2*)ab,
                                            (__nv_bfloat162*)acat, M_, 1);
    gemm_tc_kernel<<<gg, 256, GEMM_SMEM>>>(acat, wcat + 3 * (size_t)D_ * KCAT, out);
}

// round 5
// speedup vs baseline: 3.6602x; 2.3123x over previous
#include <cuda_runtime.h>
#include <cuda_bf16.h>
#include <cuda_fp16.h>
#include <cstdint>

// Problem constants (fixed by setup_inputs)
#define B_  2
#define S_  2048
#define D_  1024
#define H_  16
#define HD_ 64
#define M_  (B_ * S_)     // 4096
#define KCAT 3072         // 3x hi/lo split K

// ---------------------------------------------------------------------------
// Scratch (__device__ globals; no allocation allowed)
// ---------------------------------------------------------------------------
__device__ float g_q[(size_t)M_ * D_];
__device__ float g_k[(size_t)M_ * D_];
__device__ float g_v[(size_t)M_ * D_];
__device__ float g_attn[(size_t)M_ * D_];
__device__ __nv_bfloat16 g_xcat[(size_t)M_ * KCAT];        // [x_hi | x_lo | x_hi]
__device__ __nv_bfloat16 g_wcat[4][(size_t)D_ * KCAT];     // [W_hi | W_hi | W_lo]
__device__ __nv_bfloat16 g_acat[(size_t)M_ * KCAT];
__device__ __half g_qh[(size_t)M_ * D_];                   // fp16 q (pre-scaled)
__device__ __half g_kh[(size_t)M_ * D_];                   // fp16 k
__device__ __half g_vh[2 * (size_t)M_ * D_];               // fp16 v hi | lo planes

// ---------------------------------------------------------------------------
// Helpers
// ---------------------------------------------------------------------------
__device__ __forceinline__ uint32_t smem_u32(const void* p) {
    uint32_t a;
    asm("{ .reg .u64 t; cvta.to.shared.u64 t, %1; cvt.u32.u64 %0, t; }"
        : "=r"(a) : "l"(p));
    return a;
}
__device__ __forceinline__ uint32_t sw128(uint32_t o) { return o ^ ((o >> 3) & 0x70); }

__device__ __forceinline__ uint32_t h2_as_u32(__half2 h) {
    uint32_t u;
    asm("mov.b32 %0, %1;" : "=r"(u) : "r"(*reinterpret_cast<uint32_t*>(&h)));
    return u;
}
__device__ __forceinline__ uint32_t pack_h2(float a, float b) {
    __half2 h = __floats2half2_rn(a, b);
    return *reinterpret_cast<uint32_t*>(&h);
}

#define CP_ASYNC16(saddr, gptr) \
    asm volatile("cp.async.cg.shared.global [%0], [%1], 16;" \
                 :: "r"(saddr), "l"(gptr) : "memory")
#define CP_COMMIT() asm volatile("cp.async.commit_group;" ::: "memory")
#define CP_WAIT1()  asm volatile("cp.async.wait_group 1;" ::: "memory")
#define CP_WAIT0()  asm volatile("cp.async.wait_group 0;" ::: "memory")

#define LDMATRIX_X4(r0, r1, r2, r3, addr) \
    asm volatile("ldmatrix.sync.aligned.m8n8.x4.shared.b16 {%0,%1,%2,%3}, [%4];" \
                 : "=r"(r0), "=r"(r1), "=r"(r2), "=r"(r3) : "r"(addr))
#define LDMATRIX_X4_T(r0, r1, r2, r3, addr) \
    asm volatile("ldmatrix.sync.aligned.m8n8.x4.trans.shared.b16 {%0,%1,%2,%3}, [%4];" \
                 : "=r"(r0), "=r"(r1), "=r"(r2), "=r"(r3) : "r"(addr))

#define MMA_BF16(d, a, b) \
    asm volatile("mma.sync.aligned.m16n8k16.row.col.f32.bf16.bf16.f32 " \
                 "{%0,%1,%2,%3}, {%4,%5,%6,%7}, {%8,%9}, {%0,%1,%2,%3};" \
                 : "+f"((d)[0]), "+f"((d)[1]), "+f"((d)[2]), "+f"((d)[3]) \
                 : "r"((a)[0]), "r"((a)[1]), "r"((a)[2]), "r"((a)[3]),   \
                   "r"((b)[0]), "r"((b)[1]))
#define MMA_F16(d, a, b) \
    asm volatile("mma.sync.aligned.m16n8k16.row.col.f32.f16.f16.f32 " \
                 "{%0,%1,%2,%3}, {%4,%5,%6,%7}, {%8,%9}, {%0,%1,%2,%3};" \
                 : "+f"((d)[0]), "+f"((d)[1]), "+f"((d)[2]), "+f"((d)[3]) \
                 : "r"((a)[0]), "r"((a)[1]), "r"((a)[2]), "r"((a)[3]),   \
                   "r"((b)[0]), "r"((b)[1]))

// ---------------------------------------------------------------------------
// Split kernel: src fp32 [rows, 1024] -> dst bf16 [rows, 3072]
// aMode=1: [hi | lo | hi]   (activations);  aMode=0: [hi | hi | lo]  (weights)
// ---------------------------------------------------------------------------
__global__ void split_kernel(const float2* __restrict__ src,
                             __nv_bfloat162* __restrict__ dst,
                             int rows, int aMode)
{
    int p = blockIdx.x * blockDim.x + threadIdx.x;
    if (p >= rows * 512) return;
    int row = p >> 9;
    int cp  = p & 511;
    float2 v = src[p];
    __nv_bfloat16 h0 = __float2bfloat16(v.x);
    __nv_bfloat16 h1 = __float2bfloat16(v.y);
    __nv_bfloat16 l0 = __float2bfloat16(v.x - __bfloat162float(h0));
    __nv_bfloat16 l1 = __float2bfloat16(v.y - __bfloat162float(h1));
    __nv_bfloat162 hi; hi.x = h0; hi.y = h1;
    __nv_bfloat162 lo; lo.x = l0; lo.y = l1;
    __nv_bfloat162* drow = dst + (size_t)row * 1536;
    drow[cp]        = hi;
    drow[512 + cp]  = aMode ? lo : hi;
    drow[1024 + cp] = aMode ? hi : lo;
}

// ---------------------------------------------------------------------------
// HMMA bf16 GEMM (unchanged from round 3 — validated)
// ---------------------------------------------------------------------------
#define STAGE_BYTES 32768
#define GEMM_SMEM   (2 * STAGE_BYTES)
#define NCHUNK      (KCAT / 64)

__global__ __launch_bounds__(256) void gemm_tc_kernel(
    const __nv_bfloat16* __restrict__ A,
    const __nv_bfloat16* __restrict__ Bw,
    float* __restrict__ C)
{
    extern __shared__ char dyn[];
    const int tid  = threadIdx.x;
    const int wid  = tid >> 5;
    const int lane = tid & 31;
    const int wm   = wid >> 2;
    const int wn   = wid & 3;
    const int m0   = blockIdx.y * 128;
    const int n0   = blockIdx.x * 128;
    const uint32_t smem = smem_u32(dyn);

    const int lrow = tid >> 3;
    const int lc16 = tid & 7;
    const __nv_bfloat16* gA = A  + (size_t)(m0 + lrow) * KCAT + lc16 * 8;
    const __nv_bfloat16* gB = Bw + (size_t)(n0 + lrow) * KCAT + lc16 * 8;
    const uint32_t sA0 = smem + sw128(lrow * 128 + lc16 * 16);
    const uint32_t sB0 = sA0 + 16384;

#define PREFETCH(c, stg) do {                                                   \
    const __nv_bfloat16* pa = gA + (size_t)(c) * 64;                            \
    const __nv_bfloat16* pb = gB + (size_t)(c) * 64;                            \
    uint32_t off = (stg) * STAGE_BYTES;                                         \
    _Pragma("unroll")                                                           \
    for (int j = 0; j < 4; j++) {                                               \
        CP_ASYNC16(sA0 + off + j * 4096, pa + (size_t)j * 32 * KCAT);           \
        CP_ASYNC16(sB0 + off + j * 4096, pb + (size_t)j * 32 * KCAT);           \
    }                                                                           \
    CP_COMMIT(); } while (0)

    float acc[4][4][4];
#pragma unroll
    for (int i = 0; i < 4; i++)
#pragma unroll
        for (int j = 0; j < 4; j++)
#pragma unroll
            for (int q = 0; q < 4; q++) acc[i][j][q] = 0.f;

    const int arow = wm * 64 + (lane & 15);
    const int acb0 = (lane >> 4) * 16;
    const int brow = wn * 32 + (lane & 7) + ((lane >> 4) << 3);
    const int bcb0 = ((lane >> 3) & 1) * 16;

    PREFETCH(0, 0);

    for (int c = 0; c < NCHUNK; c++) {
        const int s = c & 1;
        const bool has_next = (c + 1 < NCHUNK);
        if (has_next) { PREFETCH(c + 1, s ^ 1); CP_WAIT1(); }
        else          { CP_WAIT0(); }
        __syncthreads();

        const uint32_t abase = smem + s * STAGE_BYTES;
        const uint32_t bbase = abase + 16384;

#pragma unroll
        for (int ks = 0; ks < 4; ks++) {
            uint32_t a[4][4], b[4][2];
#pragma unroll
            for (int mf = 0; mf < 4; mf++) {
                int row = arow + mf * 16;
                int cb  = ks * 32 + acb0;
                uint32_t addr = abase + row * 128 + (cb ^ ((row & 7) << 4));
                LDMATRIX_X4(a[mf][0], a[mf][1], a[mf][2], a[mf][3], addr);
            }
#pragma unroll
            for (int nf2 = 0; nf2 < 2; nf2++) {
                int row = brow + nf2 * 16;
                int cb  = ks * 32 + bcb0;
                uint32_t addr = bbase + row * 128 + (cb ^ ((row & 7) << 4));
                uint32_t r0, r1, r2, r3;
                LDMATRIX_X4(r0, r1, r2, r3, addr);
                b[nf2 * 2][0] = r0; b[nf2 * 2][1] = r1;
                b[nf2 * 2 + 1][0] = r2; b[nf2 * 2 + 1][1] = r3;
            }
#pragma unroll
            for (int mf = 0; mf < 4; mf++)
#pragma unroll
                for (int nf = 0; nf < 4; nf++)
                    MMA_BF16(acc[mf][nf], a[mf], b[nf]);
        }
        __syncthreads();
    }
#undef PREFETCH

#pragma unroll
    for (int mf = 0; mf < 4; mf++) {
        int r = m0 + wm * 64 + mf * 16 + (lane >> 2);
#pragma unroll
        for (int nf = 0; nf < 4; nf++) {
            int cN = n0 + wn * 32 + nf * 8 + (lane & 3) * 2;
            *(float2*)(C + (size_t)r * D_ + cN) =
                make_float2(acc[mf][nf][0], acc[mf][nf][1]);
            *(float2*)(C + (size_t)(r + 8) * D_ + cN) =
                make_float2(acc[mf][nf][2], acc[mf][nf][3]);
        }
    }
}

// ---------------------------------------------------------------------------
// RoPE + fp16 convert: q,k fp32 -> rope -> fp16 (q pre-scaled by 1/8);
// v fp32 -> fp16 hi + fp16 lo planes.
// ---------------------------------------------------------------------------
__global__ void rope_convert_kernel(
    const float2* __restrict__ q, const float2* __restrict__ k,
    const float2* __restrict__ v,
    __half2* __restrict__ qh, __half2* __restrict__ kh,
    __half2* __restrict__ vhi, __half2* __restrict__ vlo,
    const float* __restrict__ fc, const float* __restrict__ fs)
{
    int p = blockIdx.x * blockDim.x + threadIdx.x;   // pair index
    int c   = p & 511;
    int row = p >> 9;
    int s   = row & (S_ - 1);
    int j   = c & 31;
    float cv = fc[s * 32 + j];
    float sv = fs[s * 32 + j];
    float2 qv = q[p];
    qh[p] = __floats2half2_rn((qv.x * cv - qv.y * sv) * 0.125f,
                              (qv.y * cv + qv.x * sv) * 0.125f);
    float2 kv = k[p];
    kh[p] = __floats2half2_rn(kv.x * cv - kv.y * sv, kv.y * cv + kv.x * sv);
    float2 vv = v[p];
    __half2 hi = __floats2half2_rn(vv.x, vv.y);
    vhi[p] = hi;
    vlo[p] = __floats2half2_rn(vv.x - __low2float(hi), vv.y - __high2float(hi));
}

// ---------------------------------------------------------------------------
// HMMA fp16 causal flash attention.
// CTA: 128 q-rows x one (b,h). 8 warps, each owns 16 q-rows.
// K tile 128x64 fp16; V tile 256x64 (hi plane rows 0-127, lo plane 128-255).
// cp.async double-buffered. Smem = 16K (Q) + 2*(16K + 32K) = 112 KB.
// ---------------------------------------------------------------------------
#define ATT_STAGE 49152
#define ATT_SMEM  (16384 + 2 * ATT_STAGE)

__global__ __launch_bounds__(256) void attn_hmma_kernel(
    const __half* __restrict__ qh, const __half* __restrict__ kh,
    const __half* __restrict__ vh, float* __restrict__ o)
{
    extern __shared__ char dyn[];
    const int tid  = threadIdx.x;
    const int wid  = tid >> 5;
    const int lane = tid & 31;
    const int qt = 15 - blockIdx.x;          // heavy tiles first
    const int bh = blockIdx.y;
    const int b  = bh >> 4;
    const int h  = bh & 15;
    const size_t base = (size_t)b * S_ * D_ + (size_t)h * HD_;
    const uint32_t smem = smem_u32(dyn);

    const int lrow = tid >> 3;               // 0..31
    const int lc16 = tid & 7;                // 16B chunk in 128B row
    const __half* gq  = qh + base + (size_t)(qt * 128 + lrow) * D_ + lc16 * 8;
    const __half* gk  = kh + base + (size_t)lrow * D_ + lc16 * 8;
    const __half* gvh = vh + base + (size_t)lrow * D_ + lc16 * 8;
    const __half* gvl = gvh + (size_t)M_ * D_;
    const uint32_t sQ = smem + sw128(lrow * 128 + lc16 * 16);

    // Q tile (one cp.async group)
#pragma unroll
    for (int j = 0; j < 4; j++)
        CP_ASYNC16(sQ + j * 4096, gq + (size_t)j * 32 * D_);
    CP_COMMIT();

#define ATT_PREFETCH(kt, stg) do {                                              \
    uint32_t sb = smem + 16384 + (stg) * ATT_STAGE + sw128(lrow * 128 + lc16 * 16); \
    const __half* pk = gk  + (size_t)(kt) * 128 * D_;                           \
    const __half* pv = gvh + (size_t)(kt) * 128 * D_;                           \
    const __half* pl = gvl + (size_t)(kt) * 128 * D_;                           \
    _Pragma("unroll")                                                           \
    for (int j = 0; j < 4; j++) {                                               \
        CP_ASYNC16(sb +         j * 4096, pk + (size_t)j * 32 * D_);            \
        CP_ASYNC16(sb + 16384 + j * 4096, pv + (size_t)j * 32 * D_);            \
        CP_ASYNC16(sb + 32768 + j * 4096, pl + (size_t)j * 32 * D_);            \
    }                                                                           \
    CP_COMMIT(); } while (0)

    float ml = -1e30f, mh = -1e30f, ll = 0.f, lh = 0.f;
    float oacc[8][4];
#pragma unroll
    for (int i = 0; i < 8; i++)
#pragma unroll
        for (int j = 0; j < 4; j++) oacc[i][j] = 0.f;

    ATT_PREFETCH(0, 0);

    const int rowl_g = qt * 128 + wid * 16 + (lane >> 2);  // global q row (low)

    for (int kt = 0; kt <= qt; kt++) {
        const int s = kt & 1;
        if (kt < qt) { ATT_PREFETCH(kt + 1, s ^ 1); CP_WAIT1(); }
        else         { CP_WAIT0(); }
        __syncthreads();

        const uint32_t kb = smem + 16384 + s * ATT_STAGE;
        const uint32_t vb = kb + 16384;

        // ---- S = Q K^T : warp tile 16(M) x 128(N), K=64 ----
        float sacc[16][4];
#pragma unroll
        for (int nf = 0; nf < 16; nf++)
#pragma unroll
            for (int q4 = 0; q4 < 4; q4++) sacc[nf][q4] = 0.f;

#pragma unroll
        for (int ks = 0; ks < 4; ks++) {
            const int arow = wid * 16 + (lane & 15);
            uint32_t aaddr = smem + arow * 128 +
                ((ks * 32 + (lane >> 4) * 16) ^ ((arow & 7) << 4));
            uint32_t a[4];
            LDMATRIX_X4(a[0], a[1], a[2], a[3], aaddr);
#pragma unroll
            for (int nf2 = 0; nf2 < 8; nf2++) {
                const int brow = nf2 * 16 + (lane & 7) + ((lane >> 4) << 3);
                uint32_t baddr = kb + brow * 128 +
                    ((ks * 32 + ((lane >> 3) & 1) * 16) ^ ((brow & 7) << 4));
                uint32_t r0, r1, r2, r3;
                LDMATRIX_X4(r0, r1, r2, r3, baddr);
                uint32_t b0[2] = {r0, r1}, b1[2] = {r2, r3};
                MMA_F16(sacc[nf2 * 2],     a, b0);
                MMA_F16(sacc[nf2 * 2 + 1], a, b1);
            }
        }

        // ---- causal mask (diagonal tile only) ----
        if (kt == qt) {
#pragma unroll
            for (int nf = 0; nf < 16; nf++) {
                int c0 = qt * 128 + nf * 8 + (lane & 3) * 2;
                if (c0     > rowl_g)     sacc[nf][0] = -1e30f;
                if (c0 + 1 > rowl_g)     sacc[nf][1] = -1e30f;
                if (c0     > rowl_g + 8) sacc[nf][2] = -1e30f;
                if (c0 + 1 > rowl_g + 8) sacc[nf][3] = -1e30f;
            }
        }

        // ---- online softmax (row groups of 4 lanes; shfl xor 1,2) ----
        float tml = -1e30f, tmh = -1e30f;
#pragma unroll
        for (int nf = 0; nf < 16; nf++) {
            tml = fmaxf(tml, fmaxf(sacc[nf][0], sacc[nf][1]));
            tmh = fmaxf(tmh, fmaxf(sacc[nf][2], sacc[nf][3]));
        }
        tml = fmaxf(tml, __shfl_xor_sync(0xffffffffu, tml, 1));
        tml = fmaxf(tml, __shfl_xor_sync(0xffffffffu, tml, 2));
        tmh = fmaxf(tmh, __shfl_xor_sync(0xffffffffu, tmh, 1));
        tmh = fmaxf(tmh, __shfl_xor_sync(0xffffffffu, tmh, 2));

        const float mln = fmaxf(ml, tml), mhn = fmaxf(mh, tmh);
        const float scl = __expf(ml - mln), sch = __expf(mh - mhn);
        ml = mln; mh = mhn;

        uint32_t phl[16], phh[16];
        float sl = 0.f, sh = 0.f;
#pragma unroll
        for (int nf = 0; nf < 16; nf++) {
            float p0 = __expf(sacc[nf][0] - mln);
            float p1 = __expf(sacc[nf][1] - mln);
            float p2 = __expf(sacc[nf][2] - mhn);
            float p3 = __expf(sacc[nf][3] - mhn);
            sl += p0 + p1; sh += p2 + p3;
            phl[nf] = pack_h2(p0, p1);
            phh[nf] = pack_h2(p2, p3);
        }
        sl += __shfl_xor_sync(0xffffffffu, sl, 1);
        sl += __shfl_xor_sync(0xffffffffu, sl, 2);
        sh += __shfl_xor_sync(0xffffffffu, sh, 1);
        sh += __shfl_xor_sync(0xffffffffu, sh, 2);
        ll = ll * scl + sl;
        lh = lh * sch + sh;
#pragma unroll
        for (int onf = 0; onf < 8; onf++) {
            oacc[onf][0] *= scl; oacc[onf][1] *= scl;
            oacc[onf][2] *= sch; oacc[onf][3] *= sch;
        }

        // ---- O += P V  (16 k-steps: hi plane 0-7, lo plane 8-15) ----
#pragma unroll
        for (int ksp = 0; ksp < 16; ksp++) {
            const int pf = ksp & 7;
            uint32_t a[4] = { phl[2 * pf], phh[2 * pf],
                              phl[2 * pf + 1], phh[2 * pf + 1] };
            const int vrow = ksp * 16 + (lane & 7) + ((lane >> 3) & 1) * 8;
#pragma unroll
            for (int nd = 0; nd < 4; nd++) {
                uint32_t vaddr = vb + vrow * 128 +
                    ((nd * 32 + (lane >> 4) * 16) ^ ((vrow & 7) << 4));
                uint32_t r0, r1, r2, r3;
                LDMATRIX_X4_T(r0, r1, r2, r3, vaddr);
                uint32_t b0[2] = {r0, r1}, b1[2] = {r2, r3};
                MMA_F16(oacc[nd * 2],     a, b0);
                MMA_F16(oacc[nd * 2 + 1], a, b1);
            }
        }
        __syncthreads();
    }
#undef ATT_PREFETCH

    // ---- epilogue: normalize, write fp32 attn in [B,S,D] layout ----
    const float il = 1.f / ll, ih = 1.f / lh;
    float* po = o + base + (size_t)rowl_g * D_;
#pragma unroll
    for (int nf = 0; nf < 8; nf++) {
        int d = nf * 8 + (lane & 3) * 2;
        *(float2*)(po + d) = make_float2(oacc[nf][0] * il, oacc[nf][1] * il);
        *(float2*)(po + 8 * D_ + d) = make_float2(oacc[nf][2] * ih, oacc[nf][3] * ih);
    }
}

// ---------------------------------------------------------------------------
// kernel_launch
// ---------------------------------------------------------------------------
extern "C" void kernel_launch(void* const* d_in, const int* in_sizes, int n_in,
                              void* d_out, int out_size)
{
    (void)in_sizes; (void)n_in; (void)out_size;
    const float* x  = (const float*)d_in[0];
    const float* fc = (const float*)d_in[1];
    const float* fs = (const float*)d_in[2];
    const float* Ws[4] = { (const float*)d_in[3], (const float*)d_in[4],
                           (const float*)d_in[5], (const float*)d_in[6] };
    float* out = (float*)d_out;

    float *qb, *kb, *vb, *ab;
    __nv_bfloat16 *xcat, *wcat, *acat;
    __half *qhp, *khp, *vhp;
    cudaGetSymbolAddress((void**)&qb, g_q);
    cudaGetSymbolAddress((void**)&kb, g_k);
    cudaGetSymbolAddress((void**)&vb, g_v);
    cudaGetSymbolAddress((void**)&ab, g_attn);
    cudaGetSymbolAddress((void**)&xcat, g_xcat);
    cudaGetSymbolAddress((void**)&wcat, g_wcat);
    cudaGetSymbolAddress((void**)&acat, g_acat);
    cudaGetSymbolAddress((void**)&qhp, g_qh);
    cudaGetSymbolAddress((void**)&khp, g_kh);
    cudaGetSymbolAddress((void**)&vhp, g_vh);

    cudaFuncSetAttribute(gemm_tc_kernel,
                         cudaFuncAttributeMaxDynamicSharedMemorySize, GEMM_SMEM);
    cudaFuncSetAttribute(attn_hmma_kernel,
                         cudaFuncAttributeMaxDynamicSharedMemorySize, ATT_SMEM);

    split_kernel<<<(M_ * 512) / 256, 256>>>((const float2*)x,
                                            (__nv_bfloat162*)xcat, M_, 1);
    for (int w = 0; w < 4; w++)
        split_kernel<<<(D_ * 512) / 256, 256>>>((const float2*)Ws[w],
            (__nv_bfloat162*)(wcat + (size_t)w * D_ * KCAT), D_, 0);

    dim3 gg(D_ / 128, M_ / 128);   // (8, 32)
    gemm_tc_kernel<<<gg, 256, GEMM_SMEM>>>(xcat, wcat + 0 * (size_t)D_ * KCAT, qb);
    gemm_tc_kernel<<<gg, 256, GEMM_SMEM>>>(xcat, wcat + 1 * (size_t)D_ * KCAT, kb);
    gemm_tc_kernel<<<gg, 256, GEMM_SMEM>>>(xcat, wcat + 2 * (size_t)D_ * KCAT, vb);

    rope_convert_kernel<<<(M_ * D_ / 2) / 256, 256>>>(
        (const float2*)qb, (const float2*)kb, (const float2*)vb,
        (__half2*)qhp, (__half2*)khp,
        (__half2*)vhp, (__half2*)(vhp + (size_t)M_ * D_), fc, fs);

    attn_hmma_kernel<<<dim3(16, 32), 256, ATT_SMEM>>>(qhp, khp, vhp, ab);

    split_kernel<<<(M_ * 512) / 256, 256>>>((const float2*)ab,
                                            (__nv_bfloat162*)acat, M_, 1);
    gemm_tc_kernel<<<gg, 256, GEMM_SMEM>>>(acat, wcat + 3 * (size_t)D_ * KCAT, out);
}

// round 6
// speedup vs baseline: 4.7389x; 1.2947x over previous
#include <cuda_runtime.h>
#include <cuda_fp16.h>
#include <cstdint>

// Problem constants (fixed by setup_inputs)
#define B_  2
#define S_  2048
#define D_  1024
#define H_  16
#define HD_ 64
#define M_  (B_ * S_)     // 4096
#define K2  2048          // 2x fp16 hi/lo split K

// ---------------------------------------------------------------------------
// Scratch (__device__ globals; no allocation allowed)
// ---------------------------------------------------------------------------
__device__ float g_q[(size_t)M_ * D_];
__device__ float g_k[(size_t)M_ * D_];
__device__ float g_v[(size_t)M_ * D_];
__device__ float g_attn[(size_t)M_ * D_];
__device__ __half g_xc16[(size_t)M_ * K2];          // [x_hi | x_lo]
__device__ __half g_wc16[4][(size_t)D_ * K2];       // [W_hi | W_hi]
__device__ __half g_ac16[(size_t)M_ * K2];          // attn split
__device__ __half g_qh[(size_t)M_ * D_];            // fp16 q (pre-scaled)
__device__ __half g_kh[(size_t)M_ * D_];            // fp16 k
__device__ __half g_vh[2 * (size_t)M_ * D_];        // fp16 v hi | lo planes

// ---------------------------------------------------------------------------
// Helpers
// ---------------------------------------------------------------------------
__device__ __forceinline__ uint32_t smem_u32(const void* p) {
    uint32_t a;
    asm("{ .reg .u64 t; cvta.to.shared.u64 t, %1; cvt.u32.u64 %0, t; }"
        : "=r"(a) : "l"(p));
    return a;
}
__device__ __forceinline__ uint32_t sw128(uint32_t o) { return o ^ ((o >> 3) & 0x70); }

__device__ __forceinline__ uint32_t pack_h2(float a, float b) {
    __half2 h = __floats2half2_rn(a, b);
    return *reinterpret_cast<uint32_t*>(&h);
}

#define CP_ASYNC16(saddr, gptr) \
    asm volatile("cp.async.cg.shared.global [%0], [%1], 16;" \
                 :: "r"(saddr), "l"(gptr) : "memory")
#define CP_COMMIT() asm volatile("cp.async.commit_group;" ::: "memory")
#define CP_WAIT1()  asm volatile("cp.async.wait_group 1;" ::: "memory")
#define CP_WAIT0()  asm volatile("cp.async.wait_group 0;" ::: "memory")

#define LDMATRIX_X4(r0, r1, r2, r3, addr) \
    asm volatile("ldmatrix.sync.aligned.m8n8.x4.shared.b16 {%0,%1,%2,%3}, [%4];" \
                 : "=r"(r0), "=r"(r1), "=r"(r2), "=r"(r3) : "r"(addr))
#define LDMATRIX_X4_T(r0, r1, r2, r3, addr) \
    asm volatile("ldmatrix.sync.aligned.m8n8.x4.trans.shared.b16 {%0,%1,%2,%3}, [%4];" \
                 : "=r"(r0), "=r"(r1), "=r"(r2), "=r"(r3) : "r"(addr))

#define MMA_F16(d, a, b) \
    asm volatile("mma.sync.aligned.m16n8k16.row.col.f32.f16.f16.f32 " \
                 "{%0,%1,%2,%3}, {%4,%5,%6,%7}, {%8,%9}, {%0,%1,%2,%3};" \
                 : "+f"((d)[0]), "+f"((d)[1]), "+f"((d)[2]), "+f"((d)[3]) \
                 : "r"((a)[0]), "r"((a)[1]), "r"((a)[2]), "r"((a)[3]),   \
                   "r"((b)[0]), "r"((b)[1]))

// ---------------------------------------------------------------------------
// Split kernel: src fp32 [rows, 1024] -> dst fp16 [rows, 2048]
// aMode=1: [hi | lo]  (activations);  aMode=0: [hi | hi]  (weights)
// ---------------------------------------------------------------------------
__global__ void split16_kernel(const float2* __restrict__ src,
                               __half2* __restrict__ dst,
                               int rows, int aMode)
{
    int p = blockIdx.x * blockDim.x + threadIdx.x;
    if (p >= rows * 512) return;
    int row = p >> 9;
    int cp  = p & 511;
    float2 v = src[p];
    __half2 hi = __floats2half2_rn(v.x, v.y);
    __half2 lo = __floats2half2_rn(v.x - __low2float(hi),
                                   v.y - __high2float(hi));
    __half2* drow = dst + (size_t)row * 1024;    // 2048 half = 1024 half2
    drow[cp]       = hi;
    drow[512 + cp] = aMode ? lo : hi;
}

// ---------------------------------------------------------------------------
// HMMA fp16 GEMM: C[M,1024] = Ac[M,2048] @ Wc[1024,2048]^T, fp32 out.
// CTA 128(M) x 256(N), BK=64, 8 warps (2x4 -> 64x64 warp tiles),
// cp.async double-buffered. Smem per stage: A 16K + B 32K = 48K; x2 = 96K.
// ---------------------------------------------------------------------------
#define A_ST       16384
#define B_ST       32768
#define STAGE2     (A_ST + B_ST)
#define GEMM_SMEM  (2 * STAGE2)
#define NCHUNK2    (K2 / 64)            // 32

__global__ __launch_bounds__(256, 1) void gemm_f16_kernel(
    const __half* __restrict__ A,
    const __half* __restrict__ Bw,
    float* __restrict__ C)
{
    extern __shared__ char dyn[];
    const int tid  = threadIdx.x;
    const int wid  = tid >> 5;
    const int lane = tid & 31;
    const int wm   = wid >> 2;            // 0..1
    const int wn   = wid & 3;             // 0..3
    const int m0   = blockIdx.y * 128;
    const int n0   = blockIdx.x * 256;
    const uint32_t smem = smem_u32(dyn);

    const int lrow = tid >> 3;            // 0..31
    const int lc16 = tid & 7;
    const __half* gA = A  + (size_t)(m0 + lrow) * K2 + lc16 * 8;
    const __half* gB = Bw + (size_t)(n0 + lrow) * K2 + lc16 * 8;
    const uint32_t sA0 = smem + sw128(lrow * 128 + lc16 * 16);
    const uint32_t sB0 = sA0 + A_ST;

#define PREFETCH(c, stg) do {                                                   \
    const __half* pa = gA + (size_t)(c) * 64;                                   \
    const __half* pb = gB + (size_t)(c) * 64;                                   \
    uint32_t off = (stg) * STAGE2;                                              \
    _Pragma("unroll")                                                           \
    for (int j = 0; j < 4; j++)                                                 \
        CP_ASYNC16(sA0 + off + j * 4096, pa + (size_t)j * 32 * K2);             \
    _Pragma("unroll")                                                           \
    for (int j = 0; j < 8; j++)                                                 \
        CP_ASYNC16(sB0 + off + j * 4096, pb + (size_t)j * 32 * K2);             \
    CP_COMMIT(); } while (0)

    float acc[4][8][4];
#pragma unroll
    for (int i = 0; i < 4; i++)
#pragma unroll
        for (int j = 0; j < 8; j++)
#pragma unroll
            for (int q = 0; q < 4; q++) acc[i][j][q] = 0.f;

    const int arow = wm * 64 + (lane & 15);                       // + mf*16
    const int acb0 = (lane >> 4) * 16;
    const int brow0 = wn * 64 + (lane & 7) + ((lane >> 4) << 3);  // + nf2*16
    const int bcb0 = ((lane >> 3) & 1) * 16;

    PREFETCH(0, 0);

    for (int c = 0; c < NCHUNK2; c++) {
        const int s = c & 1;
        if (c + 1 < NCHUNK2) { PREFETCH(c + 1, s ^ 1); CP_WAIT1(); }
        else                 { CP_WAIT0(); }
        __syncthreads();

        const uint32_t abase = smem + s * STAGE2;
        const uint32_t bbase = abase + A_ST;

#pragma unroll
        for (int ks = 0; ks < 4; ks++) {
            uint32_t a[4][4];
#pragma unroll
            for (int mf = 0; mf < 4; mf++) {
                int row = arow + mf * 16;
                uint32_t addr = abase + row * 128 +
                    ((ks * 32 + acb0) ^ ((row & 7) << 4));
                LDMATRIX_X4(a[mf][0], a[mf][1], a[mf][2], a[mf][3], addr);
            }
#pragma unroll
            for (int nf2 = 0; nf2 < 4; nf2++) {
                int row = brow0 + nf2 * 16;
                uint32_t addr = bbase + row * 128 +
                    ((ks * 32 + bcb0) ^ ((row & 7) << 4));
                uint32_t r0, r1, r2, r3;
                LDMATRIX_X4(r0, r1, r2, r3, addr);
                uint32_t b0[2] = {r0, r1}, b1[2] = {r2, r3};
#pragma unroll
                for (int mf = 0; mf < 4; mf++) {
                    MMA_F16(acc[mf][nf2 * 2],     a[mf], b0);
                    MMA_F16(acc[mf][nf2 * 2 + 1], a[mf], b1);
                }
            }
        }
        __syncthreads();
    }
#undef PREFETCH

    // epilogue
#pragma unroll
    for (int mf = 0; mf < 4; mf++) {
        int r = m0 + wm * 64 + mf * 16 + (lane >> 2);
#pragma unroll
        for (int nf = 0; nf < 8; nf++) {
            int cN = n0 + wn * 64 + nf * 8 + (lane & 3) * 2;
            *(float2*)(C + (size_t)r * D_ + cN) =
                make_float2(acc[mf][nf][0], acc[mf][nf][1]);
            *(float2*)(C + (size_t)(r + 8) * D_ + cN) =
                make_float2(acc[mf][nf][2], acc[mf][nf][3]);
        }
    }
}

// ---------------------------------------------------------------------------
// RoPE + fp16 convert: q,k fp32 -> rope -> fp16 (q pre-scaled by 1/8);
// v fp32 -> fp16 hi + fp16 lo planes.
// ---------------------------------------------------------------------------
__global__ void rope_convert_kernel(
    const float2* __restrict__ q, const float2* __restrict__ k,
    const float2* __restrict__ v,
    __half2* __restrict__ qh, __half2* __restrict__ kh,
    __half2* __restrict__ vhi, __half2* __restrict__ vlo,
    const float* __restrict__ fc, const float* __restrict__ fs)
{
    int p = blockIdx.x * blockDim.x + threadIdx.x;   // pair index
    int c   = p & 511;
    int row = p >> 9;
    int s   = row & (S_ - 1);
    int j   = c & 31;
    float cv = fc[s * 32 + j];
    float sv = fs[s * 32 + j];
    float2 qv = q[p];
    qh[p] = __floats2half2_rn((qv.x * cv - qv.y * sv) * 0.125f,
                              (qv.y * cv + qv.x * sv) * 0.125f);
    float2 kv = k[p];
    kh[p] = __floats2half2_rn(kv.x * cv - kv.y * sv, kv.y * cv + kv.x * sv);
    float2 vv = v[p];
    __half2 hi = __floats2half2_rn(vv.x, vv.y);
    vhi[p] = hi;
    vlo[p] = __floats2half2_rn(vv.x - __low2float(hi), vv.y - __high2float(hi));
}

// ---------------------------------------------------------------------------
// HMMA fp16 causal flash attention (validated round 5; unchanged).
// ---------------------------------------------------------------------------
#define ATT_STAGE 49152
#define ATT_SMEM  (16384 + 2 * ATT_STAGE)

__global__ __launch_bounds__(256) void attn_hmma_kernel(
    const __half* __restrict__ qh, const __half* __restrict__ kh,
    const __half* __restrict__ vh, float* __restrict__ o)
{
    extern __shared__ char dyn[];
    const int tid  = threadIdx.x;
    const int wid  = tid >> 5;
    const int lane = tid & 31;
    const int qt = 15 - blockIdx.x;
    const int bh = blockIdx.y;
    const int b  = bh >> 4;
    const int h  = bh & 15;
    const size_t base = (size_t)b * S_ * D_ + (size_t)h * HD_;
    const uint32_t smem = smem_u32(dyn);

    const int lrow = tid >> 3;
    const int lc16 = tid & 7;
    const __half* gq  = qh + base + (size_t)(qt * 128 + lrow) * D_ + lc16 * 8;
    const __half* gk  = kh + base + (size_t)lrow * D_ + lc16 * 8;
    const __half* gvh = vh + base + (size_t)lrow * D_ + lc16 * 8;
    const __half* gvl = gvh + (size_t)M_ * D_;
    const uint32_t sQ = smem + sw128(lrow * 128 + lc16 * 16);

#pragma unroll
    for (int j = 0; j < 4; j++)
        CP_ASYNC16(sQ + j * 4096, gq + (size_t)j * 32 * D_);
    CP_COMMIT();

#define ATT_PREFETCH(kt, stg) do {                                              \
    uint32_t sb = smem + 16384 + (stg) * ATT_STAGE + sw128(lrow * 128 + lc16 * 16); \
    const __half* pk = gk  + (size_t)(kt) * 128 * D_;                           \
    const __half* pv = gvh + (size_t)(kt) * 128 * D_;                           \
    const __half* pl = gvl + (size_t)(kt) * 128 * D_;                           \
    _Pragma("unroll")                                                           \
    for (int j = 0; j < 4; j++) {                                               \
        CP_ASYNC16(sb +         j * 4096, pk + (size_t)j * 32 * D_);            \
        CP_ASYNC16(sb + 16384 + j * 4096, pv + (size_t)j * 32 * D_);            \
        CP_ASYNC16(sb + 32768 + j * 4096, pl + (size_t)j * 32 * D_);            \
    }                                                                           \
    CP_COMMIT(); } while (0)

    float ml = -1e30f, mh = -1e30f, ll = 0.f, lh = 0.f;
    float oacc[8][4];
#pragma unroll
    for (int i = 0; i < 8; i++)
#pragma unroll
        for (int j = 0; j < 4; j++) oacc[i][j] = 0.f;

    ATT_PREFETCH(0, 0);

    const int rowl_g = qt * 128 + wid * 16 + (lane >> 2);

    for (int kt = 0; kt <= qt; kt++) {
        const int s = kt & 1;
        if (kt < qt) { ATT_PREFETCH(kt + 1, s ^ 1); CP_WAIT1(); }
        else         { CP_WAIT0(); }
        __syncthreads();

        const uint32_t kb = smem + 16384 + s * ATT_STAGE;
        const uint32_t vb = kb + 16384;

        float sacc[16][4];
#pragma unroll
        for (int nf = 0; nf < 16; nf++)
#pragma unroll
            for (int q4 = 0; q4 < 4; q4++) sacc[nf][q4] = 0.f;

#pragma unroll
        for (int ks = 0; ks < 4; ks++) {
            const int arow = wid * 16 + (lane & 15);
            uint32_t aaddr = smem + arow * 128 +
                ((ks * 32 + (lane >> 4) * 16) ^ ((arow & 7) << 4));
            uint32_t a[4];
            LDMATRIX_X4(a[0], a[1], a[2], a[3], aaddr);
#pragma unroll
            for (int nf2 = 0; nf2 < 8; nf2++) {
                const int brow = nf2 * 16 + (lane & 7) + ((lane >> 4) << 3);
                uint32_t baddr = kb + brow * 128 +
                    ((ks * 32 + ((lane >> 3) & 1) * 16) ^ ((brow & 7) << 4));
                uint32_t r0, r1, r2, r3;
                LDMATRIX_X4(r0, r1, r2, r3, baddr);
                uint32_t b0[2] = {r0, r1}, b1[2] = {r2, r3};
                MMA_F16(sacc[nf2 * 2],     a, b0);
                MMA_F16(sacc[nf2 * 2 + 1], a, b1);
            }
        }

        if (kt == qt) {
#pragma unroll
            for (int nf = 0; nf < 16; nf++) {
                int c0 = qt * 128 + nf * 8 + (lane & 3) * 2;
                if (c0     > rowl_g)     sacc[nf][0] = -1e30f;
                if (c0 + 1 > rowl_g)     sacc[nf][1] = -1e30f;
                if (c0     > rowl_g + 8) sacc[nf][2] = -1e30f;
                if (c0 + 1 > rowl_g + 8) sacc[nf][3] = -1e30f;
            }
        }

        float tml = -1e30f, tmh = -1e30f;
#pragma unroll
        for (int nf = 0; nf < 16; nf++) {
            tml = fmaxf(tml, fmaxf(sacc[nf][0], sacc[nf][1]));
            tmh = fmaxf(tmh, fmaxf(sacc[nf][2], sacc[nf][3]));
        }
        tml = fmaxf(tml, __shfl_xor_sync(0xffffffffu, tml, 1));
        tml = fmaxf(tml, __shfl_xor_sync(0xffffffffu, tml, 2));
        tmh = fmaxf(tmh, __shfl_xor_sync(0xffffffffu, tmh, 1));
        tmh = fmaxf(tmh, __shfl_xor_sync(0xffffffffu, tmh, 2));

        const float mln = fmaxf(ml, tml), mhn = fmaxf(mh, tmh);
        const float scl = __expf(ml - mln), sch = __expf(mh - mhn);
        ml = mln; mh = mhn;

        uint32_t phl[16], phh[16];
        float sl = 0.f, sh = 0.f;
#pragma unroll
        for (int nf = 0; nf < 16; nf++) {
            float p0 = __expf(sacc[nf][0] - mln);
            float p1 = __expf(sacc[nf][1] - mln);
            float p2 = __expf(sacc[nf][2] - mhn);
            float p3 = __expf(sacc[nf][3] - mhn);
            sl += p0 + p1; sh += p2 + p3;
            phl[nf] = pack_h2(p0, p1);
            phh[nf] = pack_h2(p2, p3);
        }
        sl += __shfl_xor_sync(0xffffffffu, sl, 1);
        sl += __shfl_xor_sync(0xffffffffu, sl, 2);
        sh += __shfl_xor_sync(0xffffffffu, sh, 1);
        sh += __shfl_xor_sync(0xffffffffu, sh, 2);
        ll = ll * scl + sl;
        lh = lh * sch + sh;
#pragma unroll
        for (int onf = 0; onf < 8; onf++) {
            oacc[onf][0] *= scl; oacc[onf][1] *= scl;
            oacc[onf][2] *= sch; oacc[onf][3] *= sch;
        }

#pragma unroll
        for (int ksp = 0; ksp < 16; ksp++) {
            const int pf = ksp & 7;
            uint32_t a[4] = { phl[2 * pf], phh[2 * pf],
                              phl[2 * pf + 1], phh[2 * pf + 1] };
            const int vrow = ksp * 16 + (lane & 7) + ((lane >> 3) & 1) * 8;
#pragma unroll
            for (int nd = 0; nd < 4; nd++) {
                uint32_t vaddr = vb + vrow * 128 +
                    ((nd * 32 + (lane >> 4) * 16) ^ ((vrow & 7) << 4));
                uint32_t r0, r1, r2, r3;
                LDMATRIX_X4_T(r0, r1, r2, r3, vaddr);
                uint32_t b0[2] = {r0, r1}, b1[2] = {r2, r3};
                MMA_F16(oacc[nd * 2],     a, b0);
                MMA_F16(oacc[nd * 2 + 1], a, b1);
            }
        }
        __syncthreads();
    }
#undef ATT_PREFETCH

    const float il = 1.f / ll, ih = 1.f / lh;
    float* po = o + base + (size_t)rowl_g * D_;
#pragma unroll
    for (int nf = 0; nf < 8; nf++) {
        int d = nf * 8 + (lane & 3) * 2;
        *(float2*)(po + d) = make_float2(oacc[nf][0] * il, oacc[nf][1] * il);
        *(float2*)(po + 8 * D_ + d) = make_float2(oacc[nf][2] * ih, oacc[nf][3] * ih);
    }
}

// ---------------------------------------------------------------------------
// kernel_launch
// ---------------------------------------------------------------------------
extern "C" void kernel_launch(void* const* d_in, const int* in_sizes, int n_in,
                              void* d_out, int out_size)
{
    (void)in_sizes; (void)n_in; (void)out_size;
    const float* x  = (const float*)d_in[0];
    const float* fc = (const float*)d_in[1];
    const float* fs = (const float*)d_in[2];
    const float* Ws[4] = { (const float*)d_in[3], (const float*)d_in[4],
                           (const float*)d_in[5], (const float*)d_in[6] };
    float* out = (float*)d_out;

    float *qb, *kb, *vb, *ab;
    __half *xc, *wc, *ac, *qhp, *khp, *vhp;
    cudaGetSymbolAddress((void**)&qb, g_q);
    cudaGetSymbolAddress((void**)&kb, g_k);
    cudaGetSymbolAddress((void**)&vb, g_v);
    cudaGetSymbolAddress((void**)&ab, g_attn);
    cudaGetSymbolAddress((void**)&xc, g_xc16);
    cudaGetSymbolAddress((void**)&wc, g_wc16);
    cudaGetSymbolAddress((void**)&ac, g_ac16);
    cudaGetSymbolAddress((void**)&qhp, g_qh);
    cudaGetSymbolAddress((void**)&khp, g_kh);
    cudaGetSymbolAddress((void**)&vhp, g_vh);

    cudaFuncSetAttribute(gemm_f16_kernel,
                         cudaFuncAttributeMaxDynamicSharedMemorySize, GEMM_SMEM);
    cudaFuncSetAttribute(attn_hmma_kernel,
                         cudaFuncAttributeMaxDynamicSharedMemorySize, ATT_SMEM);

    split16_kernel<<<(M_ * 512) / 256, 256>>>((const float2*)x,
                                              (__half2*)xc, M_, 1);
    for (int w = 0; w < 4; w++)
        split16_kernel<<<(D_ * 512) / 256, 256>>>((const float2*)Ws[w],
            (__half2*)(wc + (size_t)w * D_ * K2), D_, 0);

    dim3 gg(D_ / 256, M_ / 128);   // (4, 32) = 128 CTAs
    gemm_f16_kernel<<<gg, 256, GEMM_SMEM>>>(xc, wc + 0 * (size_t)D_ * K2, qb);
    gemm_f16_kernel<<<gg, 256, GEMM_SMEM>>>(xc, wc + 1 * (size_t)D_ * K2, kb);
    gemm_f16_kernel<<<gg, 256, GEMM_SMEM>>>(xc, wc + 2 * (size_t)D_ * K2, vb);

    rope_convert_kernel<<<(M_ * D_ / 2) / 256, 256>>>(
        (const float2*)qb, (const float2*)kb, (const float2*)vb,
        (__half2*)qhp, (__half2*)khp,
        (__half2*)vhp, (__half2*)(vhp + (size_t)M_ * D_), fc, fs);

    attn_hmma_kernel<<<dim3(16, 32), 256, ATT_SMEM>>>(qhp, khp, vhp, ab);

    split16_kernel<<<(M_ * 512) / 256, 256>>>((const float2*)ab,
                                              (__half2*)ac, M_, 1);
    gemm_f16_kernel<<<gg, 256, GEMM_SMEM>>>(ac, wc + 3 * (size_t)D_ * K2, out);
}

// round 7
// speedup vs baseline: 5.0756x; 1.0711x over previous
#include <cuda_runtime.h>
#include <cuda_fp16.h>
#include <cstdint>

// Problem constants (fixed by setup_inputs)
#define B_  2
#define S_  2048
#define D_  1024
#define H_  16
#define HD_ 64
#define M_  (B_ * S_)     // 4096
#define K2  2048          // 2x fp16 hi/lo split K (A side only; B wraps mod 1024)

// ---------------------------------------------------------------------------
// Scratch (__device__ globals; no allocation allowed)
// ---------------------------------------------------------------------------
__device__ __half g_xc16[(size_t)M_ * K2];          // [x_hi | x_lo]
__device__ __half g_wc16[(size_t)4 * D_ * D_];      // Wq|Wk|Wv|Wo fp16 [4096,1024]
__device__ __half g_ac16[(size_t)M_ * K2];          // attn out [hi | lo]
__device__ __half g_qh[(size_t)M_ * D_];            // fp16 q (roped, pre-scaled)
__device__ __half g_kh[(size_t)M_ * D_];            // fp16 k (roped)
__device__ __half g_vh[2 * (size_t)M_ * D_];        // fp16 v hi | lo planes

// ---------------------------------------------------------------------------
// Helpers
// ---------------------------------------------------------------------------
__device__ __forceinline__ uint32_t smem_u32(const void* p) {
    uint32_t a;
    asm("{ .reg .u64 t; cvta.to.shared.u64 t, %1; cvt.u32.u64 %0, t; }"
        : "=r"(a) : "l"(p));
    return a;
}
__device__ __forceinline__ uint32_t sw128(uint32_t o) { return o ^ ((o >> 3) & 0x70); }

__device__ __forceinline__ uint32_t pack_h2(float a, float b) {
    __half2 h = __floats2half2_rn(a, b);
    return *reinterpret_cast<uint32_t*>(&h);
}

#define CP_ASYNC16(saddr, gptr) \
    asm volatile("cp.async.cg.shared.global [%0], [%1], 16;" \
                 :: "r"(saddr), "l"(gptr) : "memory")
#define CP_COMMIT() asm volatile("cp.async.commit_group;" ::: "memory")
#define CP_WAIT1()  asm volatile("cp.async.wait_group 1;" ::: "memory")
#define CP_WAIT0()  asm volatile("cp.async.wait_group 0;" ::: "memory")

#define LDMATRIX_X4(r0, r1, r2, r3, addr) \
    asm volatile("ldmatrix.sync.aligned.m8n8.x4.shared.b16 {%0,%1,%2,%3}, [%4];" \
                 : "=r"(r0), "=r"(r1), "=r"(r2), "=r"(r3) : "r"(addr))
#define LDMATRIX_X4_T(r0, r1, r2, r3, addr) \
    asm volatile("ldmatrix.sync.aligned.m8n8.x4.trans.shared.b16 {%0,%1,%2,%3}, [%4];" \
                 : "=r"(r0), "=r"(r1), "=r"(r2), "=r"(r3) : "r"(addr))

#define MMA_F16(d, a, b) \
    asm volatile("mma.sync.aligned.m16n8k16.row.col.f32.f16.f16.f32 " \
                 "{%0,%1,%2,%3}, {%4,%5,%6,%7}, {%8,%9}, {%0,%1,%2,%3};" \
                 : "+f"((d)[0]), "+f"((d)[1]), "+f"((d)[2]), "+f"((d)[3]) \
                 : "r"((a)[0]), "r"((a)[1]), "r"((a)[2]), "r"((a)[3]),   \
                   "r"((b)[0]), "r"((b)[1]))

// ---------------------------------------------------------------------------
// x split: fp32 [M,1024] -> fp16 [M, 2048] = [hi | lo]
// ---------------------------------------------------------------------------
__global__ void split16_kernel(const float2* __restrict__ src,
                               __half2* __restrict__ dst)
{
    int p = blockIdx.x * blockDim.x + threadIdx.x;
    int row = p >> 9;
    int cp  = p & 511;
    float2 v = src[p];
    __half2 hi = __floats2half2_rn(v.x, v.y);
    __half2 lo = __floats2half2_rn(v.x - __low2float(hi),
                                   v.y - __high2float(hi));
    __half2* drow = dst + (size_t)row * 1024;
    drow[cp]       = hi;
    drow[512 + cp] = lo;
}

// ---------------------------------------------------------------------------
// Weight convert: 4 x fp32 [1024,1024] -> fp16 [4096,1024] (no duplication)
// ---------------------------------------------------------------------------
__global__ void wconv_kernel(const float2* __restrict__ w0,
                             const float2* __restrict__ w1,
                             const float2* __restrict__ w2,
                             const float2* __restrict__ w3,
                             __half2* __restrict__ dst)
{
    int p = blockIdx.x * blockDim.x + threadIdx.x;   // 0 .. 4*512K-1
    int w = p >> 19;                                 // 512K float2 per weight
    int q = p & 524287;
    const float2* src = (w == 0) ? w0 : (w == 1) ? w1 : (w == 2) ? w2 : w3;
    float2 v = src[q];
    dst[p] = __floats2half2_rn(v.x, v.y);
}

// ---------------------------------------------------------------------------
// HMMA fp16 GEMM, fused epilogues.
// A [M, 2048] fp16 (hi|lo), B fp16 [rows,1024] with K wrap (both A-halves hit
// the same weight plane). CTA 128(M) x 256(N), BK=64, 8 warps (64x64 tiles).
// mode 0: B rows 0..3071 = Wq|Wk|Wv; epilogue = RoPE->g_qh/g_kh, split->g_vh.
// mode 1: B rows = Wo; epilogue = plain fp32 store to C.
// ---------------------------------------------------------------------------
#define A_ST       16384
#define B_ST       32768
#define STAGE2     (A_ST + B_ST)
#define GEMM_SMEM  (2 * STAGE2)
#define NCHUNK2    (K2 / 64)            // 32

__global__ __launch_bounds__(256, 1) void gemm_f16_kernel(
    const __half* __restrict__ A,
    const __half* __restrict__ Bw,
    float* __restrict__ C,
    __half* __restrict__ qh, __half* __restrict__ kh, __half* __restrict__ vh,
    const float* __restrict__ fc, const float* __restrict__ fs,
    int mode)
{
    extern __shared__ char dyn[];
    const int tid  = threadIdx.x;
    const int wid  = tid >> 5;
    const int lane = tid & 31;
    const int wm   = wid >> 2;            // 0..1
    const int wn   = wid & 3;             // 0..3
    const int m0   = blockIdx.y * 128;
    const int n0   = blockIdx.x * 256;
    const uint32_t smem = smem_u32(dyn);

    const int lrow = tid >> 3;            // 0..31
    const int lc16 = tid & 7;
    const __half* gA = A  + (size_t)(m0 + lrow) * K2 + lc16 * 8;
    const __half* gB = Bw + (size_t)(n0 + lrow) * 1024 + lc16 * 8;   // stride 1024!
    const uint32_t sA0 = smem + sw128(lrow * 128 + lc16 * 16);
    const uint32_t sB0 = sA0 + A_ST;

#define PREFETCH(c, stg) do {                                                   \
    const __half* pa = gA + (size_t)(c) * 64;                                   \
    const __half* pb = gB + (((c) * 64) & 1023);     /* K wrap: hi|hi */        \
    uint32_t off = (stg) * STAGE2;                                              \
    _Pragma("unroll")                                                           \
    for (int j = 0; j < 4; j++)                                                 \
        CP_ASYNC16(sA0 + off + j * 4096, pa + (size_t)j * 32 * K2);             \
    _Pragma("unroll")                                                           \
    for (int j = 0; j < 8; j++)                                                 \
        CP_ASYNC16(sB0 + off + j * 4096, pb + (size_t)j * 32 * 1024);           \
    CP_COMMIT(); } while (0)

    float acc[4][8][4];
#pragma unroll
    for (int i = 0; i < 4; i++)
#pragma unroll
        for (int j = 0; j < 8; j++)
#pragma unroll
            for (int q = 0; q < 4; q++) acc[i][j][q] = 0.f;

    const int arow = wm * 64 + (lane & 15);
    const int acb0 = (lane >> 4) * 16;
    const int brow0 = wn * 64 + (lane & 7) + ((lane >> 4) << 3);
    const int bcb0 = ((lane >> 3) & 1) * 16;

    PREFETCH(0, 0);

    for (int c = 0; c < NCHUNK2; c++) {
        const int s = c & 1;
        if (c + 1 < NCHUNK2) { PREFETCH(c + 1, s ^ 1); CP_WAIT1(); }
        else                 { CP_WAIT0(); }
        __syncthreads();

        const uint32_t abase = smem + s * STAGE2;
        const uint32_t bbase = abase + A_ST;

#pragma unroll
        for (int ks = 0; ks < 4; ks++) {
            uint32_t a[4][4];
#pragma unroll
            for (int mf = 0; mf < 4; mf++) {
                int row = arow + mf * 16;
                uint32_t addr = abase + row * 128 +
                    ((ks * 32 + acb0) ^ ((row & 7) << 4));
                LDMATRIX_X4(a[mf][0], a[mf][1], a[mf][2], a[mf][3], addr);
            }
#pragma unroll
            for (int nf2 = 0; nf2 < 4; nf2++) {
                int row = brow0 + nf2 * 16;
                uint32_t addr = bbase + row * 128 +
                    ((ks * 32 + bcb0) ^ ((row & 7) << 4));
                uint32_t r0, r1, r2, r3;
                LDMATRIX_X4(r0, r1, r2, r3, addr);
                uint32_t b0[2] = {r0, r1}, b1[2] = {r2, r3};
#pragma unroll
                for (int mf = 0; mf < 4; mf++) {
                    MMA_F16(acc[mf][nf2 * 2],     a[mf], b0);
                    MMA_F16(acc[mf][nf2 * 2 + 1], a[mf], b1);
                }
            }
        }
        __syncthreads();
    }
#undef PREFETCH

    if (mode == 1) {
        // plain fp32 epilogue (output projection)
#pragma unroll
        for (int mf = 0; mf < 4; mf++) {
            int r = m0 + wm * 64 + mf * 16 + (lane >> 2);
#pragma unroll
            for (int nf = 0; nf < 8; nf++) {
                int cN = n0 + wn * 64 + nf * 8 + (lane & 3) * 2;
                *(float2*)(C + (size_t)r * D_ + cN) =
                    make_float2(acc[mf][nf][0], acc[mf][nf][1]);
                *(float2*)(C + (size_t)(r + 8) * D_ + cN) =
                    make_float2(acc[mf][nf][2], acc[mf][nf][3]);
            }
        }
        return;
    }

    // mode 0: fused QKV epilogue. n0 selects weight: 0..1023 q, ..2047 k, ..3071 v
    const int w     = n0 >> 10;            // 0=q, 1=k, 2=v
    const int cbase = n0 & 1023;
#pragma unroll
    for (int mf = 0; mf < 4; mf++) {
        const int r0r = m0 + wm * 64 + mf * 16 + (lane >> 2);
#pragma unroll
        for (int nf = 0; nf < 8; nf++) {
            const int cN = cbase + wn * 64 + nf * 8 + (lane & 3) * 2;
            const int j  = (cN & 63) >> 1;     // rope pair index within head
            if (w == 2) {
                // v: hi/lo split planes
#pragma unroll
                for (int rr = 0; rr < 2; rr++) {
                    const int r = r0r + rr * 8;
                    float x0 = acc[mf][nf][rr * 2], x1 = acc[mf][nf][rr * 2 + 1];
                    __half2 hi = __floats2half2_rn(x0, x1);
                    __half2 lo = __floats2half2_rn(x0 - __low2float(hi),
                                                   x1 - __high2float(hi));
                    *(__half2*)(vh + (size_t)r * D_ + cN) = hi;
                    *(__half2*)(vh + (size_t)M_ * D_ + (size_t)r * D_ + cN) = lo;
                }
            } else {
                __half* dst = (w == 0) ? qh : kh;
                const float qs = (w == 0) ? 0.125f : 1.0f;
#pragma unroll
                for (int rr = 0; rr < 2; rr++) {
                    const int r = r0r + rr * 8;
                    const int s = r & (S_ - 1);
                    const float cv = fc[s * 32 + j];
                    const float sv = fs[s * 32 + j];
                    float x0 = acc[mf][nf][rr * 2], x1 = acc[mf][nf][rr * 2 + 1];
                    *(__half2*)(dst + (size_t)r * D_ + cN) =
                        __floats2half2_rn((x0 * cv - x1 * sv) * qs,
                                          (x1 * cv + x0 * sv) * qs);
                }
            }
        }
    }
}

// ---------------------------------------------------------------------------
// HMMA fp16 causal flash attention (validated round 5).
// Epilogue now writes hi/lo fp16 directly into split layout g_ac16 [M, 2048].
// ---------------------------------------------------------------------------
#define ATT_STAGE 49152
#define ATT_SMEM  (16384 + 2 * ATT_STAGE)

__global__ __launch_bounds__(256) void attn_hmma_kernel(
    const __half* __restrict__ qh, const __half* __restrict__ kh,
    const __half* __restrict__ vh, __half* __restrict__ oc)
{
    extern __shared__ char dyn[];
    const int tid  = threadIdx.x;
    const int wid  = tid >> 5;
    const int lane = tid & 31;
    const int qt = 15 - blockIdx.x;
    const int bh = blockIdx.y;
    const int b  = bh >> 4;
    const int h  = bh & 15;
    const size_t base = (size_t)b * S_ * D_ + (size_t)h * HD_;
    const uint32_t smem = smem_u32(dyn);

    const int lrow = tid >> 3;
    const int lc16 = tid & 7;
    const __half* gq  = qh + base + (size_t)(qt * 128 + lrow) * D_ + lc16 * 8;
    const __half* gk  = kh + base + (size_t)lrow * D_ + lc16 * 8;
    const __half* gvh = vh + base + (size_t)lrow * D_ + lc16 * 8;
    const __half* gvl = gvh + (size_t)M_ * D_;
    const uint32_t sQ = smem + sw128(lrow * 128 + lc16 * 16);

#pragma unroll
    for (int j = 0; j < 4; j++)
        CP_ASYNC16(sQ + j * 4096, gq + (size_t)j * 32 * D_);
    CP_COMMIT();

#define ATT_PREFETCH(kt, stg) do {                                              \
    uint32_t sb = smem + 16384 + (stg) * ATT_STAGE + sw128(lrow * 128 + lc16 * 16); \
    const __half* pk = gk  + (size_t)(kt) * 128 * D_;                           \
    const __half* pv = gvh + (size_t)(kt) * 128 * D_;                           \
    const __half* pl = gvl + (size_t)(kt) * 128 * D_;                           \
    _Pragma("unroll")                                                           \
    for (int j = 0; j < 4; j++) {                                               \
        CP_ASYNC16(sb +         j * 4096, pk + (size_t)j * 32 * D_);            \
        CP_ASYNC16(sb + 16384 + j * 4096, pv + (size_t)j * 32 * D_);            \
        CP_ASYNC16(sb + 32768 + j * 4096, pl + (size_t)j * 32 * D_);            \
    }                                                                           \
    CP_COMMIT(); } while (0)

    float ml = -1e30f, mh = -1e30f, ll = 0.f, lh = 0.f;
    float oacc[8][4];
#pragma unroll
    for (int i = 0; i < 8; i++)
#pragma unroll
        for (int j = 0; j < 4; j++) oacc[i][j] = 0.f;

    ATT_PREFETCH(0, 0);

    const int rowl_g = qt * 128 + wid * 16 + (lane >> 2);

    for (int kt = 0; kt <= qt; kt++) {
        const int s = kt & 1;
        if (kt < qt) { ATT_PREFETCH(kt + 1, s ^ 1); CP_WAIT1(); }
        else         { CP_WAIT0(); }
        __syncthreads();

        const uint32_t kb = smem + 16384 + s * ATT_STAGE;
        const uint32_t vb = kb + 16384;

        float sacc[16][4];
#pragma unroll
        for (int nf = 0; nf < 16; nf++)
#pragma unroll
            for (int q4 = 0; q4 < 4; q4++) sacc[nf][q4] = 0.f;

#pragma unroll
        for (int ks = 0; ks < 4; ks++) {
            const int arow = wid * 16 + (lane & 15);
            uint32_t aaddr = smem + arow * 128 +
                ((ks * 32 + (lane >> 4) * 16) ^ ((arow & 7) << 4));
            uint32_t a[4];
            LDMATRIX_X4(a[0], a[1], a[2], a[3], aaddr);
#pragma unroll
            for (int nf2 = 0; nf2 < 8; nf2++) {
                const int brow = nf2 * 16 + (lane & 7) + ((lane >> 4) << 3);
                uint32_t baddr = kb + brow * 128 +
                    ((ks * 32 + ((lane >> 3) & 1) * 16) ^ ((brow & 7) << 4));
                uint32_t r0, r1, r2, r3;
                LDMATRIX_X4(r0, r1, r2, r3, baddr);
                uint32_t b0[2] = {r0, r1}, b1[2] = {r2, r3};
                MMA_F16(sacc[nf2 * 2],     a, b0);
                MMA_F16(sacc[nf2 * 2 + 1], a, b1);
            }
        }

        if (kt == qt) {
#pragma unroll
            for (int nf = 0; nf < 16; nf++) {
                int c0 = qt * 128 + nf * 8 + (lane & 3) * 2;
                if (c0     > rowl_g)     sacc[nf][0] = -1e30f;
                if (c0 + 1 > rowl_g)     sacc[nf][1] = -1e30f;
                if (c0     > rowl_g + 8) sacc[nf][2] = -1e30f;
                if (c0 + 1 > rowl_g + 8) sacc[nf][3] = -1e30f;
            }
        }

        float tml = -1e30f, tmh = -1e30f;
#pragma unroll
        for (int nf = 0; nf < 16; nf++) {
            tml = fmaxf(tml, fmaxf(sacc[nf][0], sacc[nf][1]));
            tmh = fmaxf(tmh, fmaxf(sacc[nf][2], sacc[nf][3]));
        }
        tml = fmaxf(tml, __shfl_xor_sync(0xffffffffu, tml, 1));
        tml = fmaxf(tml, __shfl_xor_sync(0xffffffffu, tml, 2));
        tmh = fmaxf(tmh, __shfl_xor_sync(0xffffffffu, tmh, 1));
        tmh = fmaxf(tmh, __shfl_xor_sync(0xffffffffu, tmh, 2));

        const float mln = fmaxf(ml, tml), mhn = fmaxf(mh, tmh);
        const float scl = __expf(ml - mln), sch = __expf(mh - mhn);
        ml = mln; mh = mhn;

        uint32_t phl[16], phh[16];
        float sl = 0.f, sh = 0.f;
#pragma unroll
        for (int nf = 0; nf < 16; nf++) {
            float p0 = __expf(sacc[nf][0] - mln);
            float p1 = __expf(sacc[nf][1] - mln);
            float p2 = __expf(sacc[nf][2] - mhn);
            float p3 = __expf(sacc[nf][3] - mhn);
            sl += p0 + p1; sh += p2 + p3;
            phl[nf] = pack_h2(p0, p1);
            phh[nf] = pack_h2(p2, p3);
        }
        sl += __shfl_xor_sync(0xffffffffu, sl, 1);
        sl += __shfl_xor_sync(0xffffffffu, sl, 2);
        sh += __shfl_xor_sync(0xffffffffu, sh, 1);
        sh += __shfl_xor_sync(0xffffffffu, sh, 2);
        ll = ll * scl + sl;
        lh = lh * sch + sh;
#pragma unroll
        for (int onf = 0; onf < 8; onf++) {
            oacc[onf][0] *= scl; oacc[onf][1] *= scl;
            oacc[onf][2] *= sch; oacc[onf][3] *= sch;
        }

#pragma unroll
        for (int ksp = 0; ksp < 16; ksp++) {
            const int pf = ksp & 7;
            uint32_t a[4] = { phl[2 * pf], phh[2 * pf],
                              phl[2 * pf + 1], phh[2 * pf + 1] };
            const int vrow = ksp * 16 + (lane & 7) + ((lane >> 3) & 1) * 8;
#pragma unroll
            for (int nd = 0; nd < 4; nd++) {
                uint32_t vaddr = vb + vrow * 128 +
                    ((nd * 32 + (lane >> 4) * 16) ^ ((vrow & 7) << 4));
                uint32_t r0, r1, r2, r3;
                LDMATRIX_X4_T(r0, r1, r2, r3, vaddr);
                uint32_t b0[2] = {r0, r1}, b1[2] = {r2, r3};
                MMA_F16(oacc[nd * 2],     a, b0);
                MMA_F16(oacc[nd * 2 + 1], a, b1);
            }
        }
        __syncthreads();
    }
#undef ATT_PREFETCH

    // ---- epilogue: normalize, hi/lo split, write into g_ac16 [M, 2048] ----
    const float il = 1.f / ll, ih = 1.f / lh;
    const int rowg = b * S_ + rowl_g;               // global row (low of pair)
#pragma unroll
    for (int nf = 0; nf < 8; nf++) {
        const int col = h * HD_ + nf * 8 + (lane & 3) * 2;
#pragma unroll
        for (int rr = 0; rr < 2; rr++) {
            const int r = rowg + rr * 8;
            float x0 = oacc[nf][rr * 2]     * (rr ? ih : il);
            float x1 = oacc[nf][rr * 2 + 1] * (rr ? ih : il);
            __half2 hi = __floats2half2_rn(x0, x1);
            __half2 lo = __floats2half2_rn(x0 - __low2float(hi),
                                           x1 - __high2float(hi));
            *(__half2*)(oc + (size_t)r * K2 + col)        = hi;
            *(__half2*)(oc + (size_t)r * K2 + 1024 + col) = lo;
        }
    }
}

// ---------------------------------------------------------------------------
// kernel_launch
// ---------------------------------------------------------------------------
extern "C" void kernel_launch(void* const* d_in, const int* in_sizes, int n_in,
                              void* d_out, int out_size)
{
    (void)in_sizes; (void)n_in; (void)out_size;
    const float* x  = (const float*)d_in[0];
    const float* fc = (const float*)d_in[1];
    const float* fs = (const float*)d_in[2];
    float* out = (float*)d_out;

    __half *xc, *wc, *ac, *qhp, *khp, *vhp;
    cudaGetSymbolAddress((void**)&xc, g_xc16);
    cudaGetSymbolAddress((void**)&wc, g_wc16);
    cudaGetSymbolAddress((void**)&ac, g_ac16);
    cudaGetSymbolAddress((void**)&qhp, g_qh);
    cudaGetSymbolAddress((void**)&khp, g_kh);
    cudaGetSymbolAddress((void**)&vhp, g_vh);

    cudaFuncSetAttribute(gemm_f16_kernel,
                         cudaFuncAttributeMaxDynamicSharedMemorySize, GEMM_SMEM);
    cudaFuncSetAttribute(attn_hmma_kernel,
                         cudaFuncAttributeMaxDynamicSharedMemorySize, ATT_SMEM);

    // x -> [hi|lo] fp16
    split16_kernel<<<(M_ * 512) / 256, 256>>>((const float2*)x, (__half2*)xc);
    // Wq|Wk|Wv|Wo -> fp16 (no duplication)
    wconv_kernel<<<(4 * 1024 * 512) / 256, 256>>>(
        (const float2*)d_in[3], (const float2*)d_in[4],
        (const float2*)d_in[5], (const float2*)d_in[6], (__half2*)wc);

    // Fused QKV projection + RoPE + v split (grid 12 x 32)
    gemm_f16_kernel<<<dim3(12, M_ / 128), 256, GEMM_SMEM>>>(
        xc, wc, nullptr, qhp, khp, vhp, fc, fs, 0);

    // Flash attention -> split fp16 attn directly
    attn_hmma_kernel<<<dim3(16, 32), 256, ATT_SMEM>>>(qhp, khp, vhp, ac);

    // Output projection (grid 4 x 32)
    gemm_f16_kernel<<<dim3(4, M_ / 128), 256, GEMM_SMEM>>>(
        ac, wc + (size_t)3 * D_ * D_, out, nullptr, nullptr, nullptr,
        nullptr, nullptr, 1);
}

// round 8
// speedup vs baseline: 5.3901x; 1.0620x over previous
#include <cuda_runtime.h>
#include <cuda_fp16.h>
#include <cstdint>

// Problem constants (fixed by setup_inputs)
#define B_  2
#define S_  2048
#define D_  1024
#define H_  16
#define HD_ 64
#define M_  (B_ * S_)     // 4096
#define K2  2048          // 2x fp16 hi/lo split K (A side only; B wraps mod 1024)

// ---------------------------------------------------------------------------
// Scratch (__device__ globals; no allocation allowed)
// ---------------------------------------------------------------------------
__device__ __half g_xc16[(size_t)M_ * K2];          // [x_hi | x_lo]
__device__ __half g_wc16[(size_t)4 * D_ * D_];      // Wq|Wk|Wv|Wo fp16 [4096,1024]
__device__ __half g_ac16[(size_t)M_ * K2];          // attn out [hi | lo]
__device__ __half g_qh[(size_t)M_ * D_];            // fp16 q (roped, pre-scaled)
__device__ __half g_kh[(size_t)M_ * D_];            // fp16 k (roped)
__device__ __half g_vh[(size_t)M_ * D_];            // fp16 v (single plane)

// ---------------------------------------------------------------------------
// Helpers
// ---------------------------------------------------------------------------
__device__ __forceinline__ uint32_t smem_u32(const void* p) {
    uint32_t a;
    asm("{ .reg .u64 t; cvta.to.shared.u64 t, %1; cvt.u32.u64 %0, t; }"
        : "=r"(a) : "l"(p));
    return a;
}
__device__ __forceinline__ uint32_t sw128(uint32_t o) { return o ^ ((o >> 3) & 0x70); }

__device__ __forceinline__ uint32_t pack_h2(float a, float b) {
    __half2 h = __floats2half2_rn(a, b);
    return *reinterpret_cast<uint32_t*>(&h);
}

#define CP_ASYNC16(saddr, gptr) \
    asm volatile("cp.async.cg.shared.global [%0], [%1], 16;" \
                 :: "r"(saddr), "l"(gptr) : "memory")
#define CP_COMMIT() asm volatile("cp.async.commit_group;" ::: "memory")
#define CP_WAIT1()  asm volatile("cp.async.wait_group 1;" ::: "memory")
#define CP_WAIT0()  asm volatile("cp.async.wait_group 0;" ::: "memory")

#define LDMATRIX_X4(r0, r1, r2, r3, addr) \
    asm volatile("ldmatrix.sync.aligned.m8n8.x4.shared.b16 {%0,%1,%2,%3}, [%4];" \
                 : "=r"(r0), "=r"(r1), "=r"(r2), "=r"(r3) : "r"(addr))
#define LDMATRIX_X4_T(r0, r1, r2, r3, addr) \
    asm volatile("ldmatrix.sync.aligned.m8n8.x4.trans.shared.b16 {%0,%1,%2,%3}, [%4];" \
                 : "=r"(r0), "=r"(r1), "=r"(r2), "=r"(r3) : "r"(addr))

#define MMA_F16(d, a, b) \
    asm volatile("mma.sync.aligned.m16n8k16.row.col.f32.f16.f16.f32 " \
                 "{%0,%1,%2,%3}, {%4,%5,%6,%7}, {%8,%9}, {%0,%1,%2,%3};" \
                 : "+f"((d)[0]), "+f"((d)[1]), "+f"((d)[2]), "+f"((d)[3]) \
                 : "r"((a)[0]), "r"((a)[1]), "r"((a)[2]), "r"((a)[3]),   \
                   "r"((b)[0]), "r"((b)[1]))

// ---------------------------------------------------------------------------
// x split: fp32 [M,1024] -> fp16 [M, 2048] = [hi | lo]
// ---------------------------------------------------------------------------
__global__ void split16_kernel(const float2* __restrict__ src,
                               __half2* __restrict__ dst)
{
    int p = blockIdx.x * blockDim.x + threadIdx.x;
    int row = p >> 9;
    int cp  = p & 511;
    float2 v = src[p];
    __half2 hi = __floats2half2_rn(v.x, v.y);
    __half2 lo = __floats2half2_rn(v.x - __low2float(hi),
                                   v.y - __high2float(hi));
    __half2* drow = dst + (size_t)row * 1024;
    drow[cp]       = hi;
    drow[512 + cp] = lo;
}

// ---------------------------------------------------------------------------
// Weight convert: 4 x fp32 [1024,1024] -> fp16 [4096,1024]
// ---------------------------------------------------------------------------
__global__ void wconv_kernel(const float2* __restrict__ w0,
                             const float2* __restrict__ w1,
                             const float2* __restrict__ w2,
                             const float2* __restrict__ w3,
                             __half2* __restrict__ dst)
{
    int p = blockIdx.x * blockDim.x + threadIdx.x;
    int w = p >> 19;
    int q = p & 524287;
    const float2* src = (w == 0) ? w0 : (w == 1) ? w1 : (w == 2) ? w2 : w3;
    float2 v = src[q];
    dst[p] = __floats2half2_rn(v.x, v.y);
}

// ---------------------------------------------------------------------------
// HMMA fp16 GEMM, 3-stage cp.async pipeline, fused epilogues.
// A [M,2048] fp16 (hi|lo), B fp16 [rows,1024] K-wrapped.
// CTA 128(M) x 256(N), BK=64, 8 warps (64x64 tiles).
// mode 0: QKV fused (RoPE q/k, plain v);  mode 1: fp32 out.
// ---------------------------------------------------------------------------
#define A_ST       16384
#define B_ST       32768
#define STAGE2     (A_ST + B_ST)
#define GEMM_SMEM  (3 * STAGE2)          // 144 KB
#define NCHUNK2    (K2 / 64)             // 32

__global__ __launch_bounds__(256, 1) void gemm_f16_kernel(
    const __half* __restrict__ A,
    const __half* __restrict__ Bw,
    float* __restrict__ C,
    __half* __restrict__ qh, __half* __restrict__ kh, __half* __restrict__ vh,
    const float* __restrict__ fc, const float* __restrict__ fs,
    int mode)
{
    extern __shared__ char dyn[];
    const int tid  = threadIdx.x;
    const int wid  = tid >> 5;
    const int lane = tid & 31;
    const int wm   = wid >> 2;
    const int wn   = wid & 3;
    const int m0   = blockIdx.y * 128;
    const int n0   = blockIdx.x * 256;
    const uint32_t smem = smem_u32(dyn);

    const int lrow = tid >> 3;
    const int lc16 = tid & 7;
    const __half* gA = A  + (size_t)(m0 + lrow) * K2 + lc16 * 8;
    const __half* gB = Bw + (size_t)(n0 + lrow) * 1024 + lc16 * 8;
    const uint32_t sA0 = smem + sw128(lrow * 128 + lc16 * 16);
    const uint32_t sB0 = sA0 + A_ST;

#define PREFETCH(c, stg) do {                                                   \
    const __half* pa = gA + (size_t)(c) * 64;                                   \
    const __half* pb = gB + (((c) * 64) & 1023);                                \
    uint32_t off = (stg) * STAGE2;                                              \
    _Pragma("unroll")                                                           \
    for (int j = 0; j < 4; j++)                                                 \
        CP_ASYNC16(sA0 + off + j * 4096, pa + (size_t)j * 32 * K2);             \
    _Pragma("unroll")                                                           \
    for (int j = 0; j < 8; j++)                                                 \
        CP_ASYNC16(sB0 + off + j * 4096, pb + (size_t)j * 32 * 1024);           \
    CP_COMMIT(); } while (0)

    float acc[4][8][4];
#pragma unroll
    for (int i = 0; i < 4; i++)
#pragma unroll
        for (int j = 0; j < 8; j++)
#pragma unroll
            for (int q = 0; q < 4; q++) acc[i][j][q] = 0.f;

    const int arow = wm * 64 + (lane & 15);
    const int acb0 = (lane >> 4) * 16;
    const int brow0 = wn * 64 + (lane & 7) + ((lane >> 4) << 3);
    const int bcb0 = ((lane >> 3) & 1) * 16;

    PREFETCH(0, 0);
    PREFETCH(1, 1);

    int s = 0, sp = 2;
    for (int c = 0; c < NCHUNK2; c++) {
        if (c + 1 < NCHUNK2) CP_WAIT1(); else CP_WAIT0();
        __syncthreads();
        if (c + 2 < NCHUNK2) PREFETCH(c + 2, sp);

        const uint32_t abase = smem + s * STAGE2;
        const uint32_t bbase = abase + A_ST;

#pragma unroll
        for (int ks = 0; ks < 4; ks++) {
            uint32_t a[4][4];
#pragma unroll
            for (int mf = 0; mf < 4; mf++) {
                int row = arow + mf * 16;
                uint32_t addr = abase + row * 128 +
                    ((ks * 32 + acb0) ^ ((row & 7) << 4));
                LDMATRIX_X4(a[mf][0], a[mf][1], a[mf][2], a[mf][3], addr);
            }
#pragma unroll
            for (int nf2 = 0; nf2 < 4; nf2++) {
                int row = brow0 + nf2 * 16;
                uint32_t addr = bbase + row * 128 +
                    ((ks * 32 + bcb0) ^ ((row & 7) << 4));
                uint32_t r0, r1, r2, r3;
                LDMATRIX_X4(r0, r1, r2, r3, addr);
                uint32_t b0[2] = {r0, r1}, b1[2] = {r2, r3};
#pragma unroll
                for (int mf = 0; mf < 4; mf++) {
                    MMA_F16(acc[mf][nf2 * 2],     a[mf], b0);
                    MMA_F16(acc[mf][nf2 * 2 + 1], a[mf], b1);
                }
            }
        }
        s  = (s  == 2) ? 0 : s + 1;
        sp = (sp == 2) ? 0 : sp + 1;
    }
#undef PREFETCH

    if (mode == 1) {
#pragma unroll
        for (int mf = 0; mf < 4; mf++) {
            int r = m0 + wm * 64 + mf * 16 + (lane >> 2);
#pragma unroll
            for (int nf = 0; nf < 8; nf++) {
                int cN = n0 + wn * 64 + nf * 8 + (lane & 3) * 2;
                *(float2*)(C + (size_t)r * D_ + cN) =
                    make_float2(acc[mf][nf][0], acc[mf][nf][1]);
                *(float2*)(C + (size_t)(r + 8) * D_ + cN) =
                    make_float2(acc[mf][nf][2], acc[mf][nf][3]);
            }
        }
        return;
    }

    // mode 0: fused QKV epilogue
    const int w     = n0 >> 10;            // 0=q, 1=k, 2=v
    const int cbase = n0 & 1023;
#pragma unroll
    for (int mf = 0; mf < 4; mf++) {
        const int r0r = m0 + wm * 64 + mf * 16 + (lane >> 2);
#pragma unroll
        for (int nf = 0; nf < 8; nf++) {
            const int cN = cbase + wn * 64 + nf * 8 + (lane & 3) * 2;
            const int j  = (cN & 63) >> 1;
            if (w == 2) {
#pragma unroll
                for (int rr = 0; rr < 2; rr++) {
                    const int r = r0r + rr * 8;
                    *(__half2*)(vh + (size_t)r * D_ + cN) =
                        __floats2half2_rn(acc[mf][nf][rr * 2],
                                          acc[mf][nf][rr * 2 + 1]);
                }
            } else {
                __half* dst = (w == 0) ? qh : kh;
                const float qs = (w == 0) ? 0.125f : 1.0f;
#pragma unroll
                for (int rr = 0; rr < 2; rr++) {
                    const int r = r0r + rr * 8;
                    const int srow = r & (S_ - 1);
                    const float cv = fc[srow * 32 + j];
                    const float sv = fs[srow * 32 + j];
                    float x0 = acc[mf][nf][rr * 2], x1 = acc[mf][nf][rr * 2 + 1];
                    *(__half2*)(dst + (size_t)r * D_ + cN) =
                        __floats2half2_rn((x0 * cv - x1 * sv) * qs,
                                          (x1 * cv + x0 * sv) * qs);
                }
            }
        }
    }
}

// ---------------------------------------------------------------------------
// HMMA fp16 causal flash attention, 3-stage pipeline, single-plane V.
// CTA: 128 q-rows x one (b,h). 8 warps. Smem = Q 16K + 3 x (K 16K + V 16K).
// ---------------------------------------------------------------------------
#define ATT_STAGE 32768
#define ATT_SMEM  (16384 + 3 * ATT_STAGE)   // 112 KB

__global__ __launch_bounds__(256) void attn_hmma_kernel(
    const __half* __restrict__ qh, const __half* __restrict__ kh,
    const __half* __restrict__ vh, __half* __restrict__ oc)
{
    extern __shared__ char dyn[];
    const int tid  = threadIdx.x;
    const int wid  = tid >> 5;
    const int lane = tid & 31;
    const int qt = 15 - blockIdx.x;
    const int bh = blockIdx.y;
    const int b  = bh >> 4;
    const int h  = bh & 15;
    const size_t base = (size_t)b * S_ * D_ + (size_t)h * HD_;
    const uint32_t smem = smem_u32(dyn);

    const int lrow = tid >> 3;
    const int lc16 = tid & 7;
    const __half* gq = qh + base + (size_t)(qt * 128 + lrow) * D_ + lc16 * 8;
    const __half* gk = kh + base + (size_t)lrow * D_ + lc16 * 8;
    const __half* gv = vh + base + (size_t)lrow * D_ + lc16 * 8;
    const uint32_t sQ = smem + sw128(lrow * 128 + lc16 * 16);

#pragma unroll
    for (int j = 0; j < 4; j++)
        CP_ASYNC16(sQ + j * 4096, gq + (size_t)j * 32 * D_);
    CP_COMMIT();

#define ATT_PREFETCH(kt, stg) do {                                              \
    uint32_t sb = smem + 16384 + (stg) * ATT_STAGE + sw128(lrow * 128 + lc16 * 16); \
    const __half* pk = gk + (size_t)(kt) * 128 * D_;                             \
    const __half* pv = gv + (size_t)(kt) * 128 * D_;                             \
    _Pragma("unroll")                                                           \
    for (int j = 0; j < 4; j++) {                                               \
        CP_ASYNC16(sb +         j * 4096, pk + (size_t)j * 32 * D_);            \
        CP_ASYNC16(sb + 16384 + j * 4096, pv + (size_t)j * 32 * D_);            \
    }                                                                           \
    CP_COMMIT(); } while (0)

    float ml = -1e30f, mh = -1e30f, ll = 0.f, lh = 0.f;
    float oacc[8][4];
#pragma unroll
    for (int i = 0; i < 8; i++)
#pragma unroll
        for (int j = 0; j < 4; j++) oacc[i][j] = 0.f;

    ATT_PREFETCH(0, 0);
    if (qt >= 1) ATT_PREFETCH(1, 1);

    const int rowl_g = qt * 128 + wid * 16 + (lane >> 2);

    int s = 0, sp = 2;
    for (int kt = 0; kt <= qt; kt++) {
        if (kt + 1 <= qt) CP_WAIT1(); else CP_WAIT0();
        __syncthreads();
        if (kt + 2 <= qt) ATT_PREFETCH(kt + 2, sp);

        const uint32_t kb = smem + 16384 + s * ATT_STAGE;
        const uint32_t vb = kb + 16384;

        float sacc[16][4];
#pragma unroll
        for (int nf = 0; nf < 16; nf++)
#pragma unroll
            for (int q4 = 0; q4 < 4; q4++) sacc[nf][q4] = 0.f;

#pragma unroll
        for (int ks = 0; ks < 4; ks++) {
            const int arow = wid * 16 + (lane & 15);
            uint32_t aaddr = smem + arow * 128 +
                ((ks * 32 + (lane >> 4) * 16) ^ ((arow & 7) << 4));
            uint32_t a[4];
            LDMATRIX_X4(a[0], a[1], a[2], a[3], aaddr);
#pragma unroll
            for (int nf2 = 0; nf2 < 8; nf2++) {
                const int brow = nf2 * 16 + (lane & 7) + ((lane >> 4) << 3);
                uint32_t baddr = kb + brow * 128 +
                    ((ks * 32 + ((lane >> 3) & 1) * 16) ^ ((brow & 7) << 4));
                uint32_t r0, r1, r2, r3;
                LDMATRIX_X4(r0, r1, r2, r3, baddr);
                uint32_t b0[2] = {r0, r1}, b1[2] = {r2, r3};
                MMA_F16(sacc[nf2 * 2],     a, b0);
                MMA_F16(sacc[nf2 * 2 + 1], a, b1);
            }
        }

        if (kt == qt) {
#pragma unroll
            for (int nf = 0; nf < 16; nf++) {
                int c0 = qt * 128 + nf * 8 + (lane & 3) * 2;
                if (c0     > rowl_g)     sacc[nf][0] = -1e30f;
                if (c0 + 1 > rowl_g)     sacc[nf][1] = -1e30f;
                if (c0     > rowl_g + 8) sacc[nf][2] = -1e30f;
                if (c0 + 1 > rowl_g + 8) sacc[nf][3] = -1e30f;
            }
        }

        float tml = -1e30f, tmh = -1e30f;
#pragma unroll
        for (int nf = 0; nf < 16; nf++) {
            tml = fmaxf(tml, fmaxf(sacc[nf][0], sacc[nf][1]));
            tmh = fmaxf(tmh, fmaxf(sacc[nf][2], sacc[nf][3]));
        }
        tml = fmaxf(tml, __shfl_xor_sync(0xffffffffu, tml, 1));
        tml = fmaxf(tml, __shfl_xor_sync(0xffffffffu, tml, 2));
        tmh = fmaxf(tmh, __shfl_xor_sync(0xffffffffu, tmh, 1));
        tmh = fmaxf(tmh, __shfl_xor_sync(0xffffffffu, tmh, 2));

        const float mln = fmaxf(ml, tml), mhn = fmaxf(mh, tmh);
        const float scl = __expf(ml - mln), sch = __expf(mh - mhn);
        ml = mln; mh = mhn;

        uint32_t phl[16], phh[16];
        float sl = 0.f, sh = 0.f;
#pragma unroll
        for (int nf = 0; nf < 16; nf++) {
            float p0 = __expf(sacc[nf][0] - mln);
            float p1 = __expf(sacc[nf][1] - mln);
            float p2 = __expf(sacc[nf][2] - mhn);
            float p3 = __expf(sacc[nf][3] - mhn);
            sl += p0 + p1; sh += p2 + p3;
            phl[nf] = pack_h2(p0, p1);
            phh[nf] = pack_h2(p2, p3);
        }
        sl += __shfl_xor_sync(0xffffffffu, sl, 1);
        sl += __shfl_xor_sync(0xffffffffu, sl, 2);
        sh += __shfl_xor_sync(0xffffffffu, sh, 1);
        sh += __shfl_xor_sync(0xffffffffu, sh, 2);
        ll = ll * scl + sl;
        lh = lh * sch + sh;
#pragma unroll
        for (int onf = 0; onf < 8; onf++) {
            oacc[onf][0] *= scl; oacc[onf][1] *= scl;
            oacc[onf][2] *= sch; oacc[onf][3] *= sch;
        }

        // ---- O += P V  (8 k-steps, single plane) ----
#pragma unroll
        for (int ksp = 0; ksp < 8; ksp++) {
            uint32_t a[4] = { phl[2 * ksp], phh[2 * ksp],
                              phl[2 * ksp + 1], phh[2 * ksp + 1] };
            const int vrow = ksp * 16 + (lane & 7) + ((lane >> 3) & 1) * 8;
#pragma unroll
            for (int nd = 0; nd < 4; nd++) {
                uint32_t vaddr = vb + vrow * 128 +
                    ((nd * 32 + (lane >> 4) * 16) ^ ((vrow & 7) << 4));
                uint32_t r0, r1, r2, r3;
                LDMATRIX_X4_T(r0, r1, r2, r3, vaddr);
                uint32_t b0[2] = {r0, r1}, b1[2] = {r2, r3};
                MMA_F16(oacc[nd * 2],     a, b0);
                MMA_F16(oacc[nd * 2 + 1], a, b1);
            }
        }
        s  = (s  == 2) ? 0 : s + 1;
        sp = (sp == 2) ? 0 : sp + 1;
    }
#undef ATT_PREFETCH

    // ---- epilogue: normalize, hi/lo split, write into g_ac16 [M, 2048] ----
    const float il = 1.f / ll, ih = 1.f / lh;
    const int rowg = b * S_ + rowl_g;
#pragma unroll
    for (int nf = 0; nf < 8; nf++) {
        const int col = h * HD_ + nf * 8 + (lane & 3) * 2;
#pragma unroll
        for (int rr = 0; rr < 2; rr++) {
            const int r = rowg + rr * 8;
            float x0 = oacc[nf][rr * 2]     * (rr ? ih : il);
            float x1 = oacc[nf][rr * 2 + 1] * (rr ? ih : il);
            __half2 hi = __floats2half2_rn(x0, x1);
            __half2 lo = __floats2half2_rn(x0 - __low2float(hi),
                                           x1 - __high2float(hi));
            *(__half2*)(oc + (size_t)r * K2 + col)        = hi;
            *(__half2*)(oc + (size_t)r * K2 + 1024 + col) = lo;
        }
    }
}

// ---------------------------------------------------------------------------
// kernel_launch
// ---------------------------------------------------------------------------
extern "C" void kernel_launch(void* const* d_in, const int* in_sizes, int n_in,
                              void* d_out, int out_size)
{
    (void)in_sizes; (void)n_in; (void)out_size;
    const float* x  = (const float*)d_in[0];
    const float* fc = (const float*)d_in[1];
    const float* fs = (const float*)d_in[2];
    float* out = (float*)d_out;

    __half *xc, *wc, *ac, *qhp, *khp, *vhp;
    cudaGetSymbolAddress((void**)&xc, g_xc16);
    cudaGetSymbolAddress((void**)&wc, g_wc16);
    cudaGetSymbolAddress((void**)&ac, g_ac16);
    cudaGetSymbolAddress((void**)&qhp, g_qh);
    cudaGetSymbolAddress((void**)&khp, g_kh);
    cudaGetSymbolAddress((void**)&vhp, g_vh);

    cudaFuncSetAttribute(gemm_f16_kernel,
                         cudaFuncAttributeMaxDynamicSharedMemorySize, GEMM_SMEM);
    cudaFuncSetAttribute(attn_hmma_kernel,
                         cudaFuncAttributeMaxDynamicSharedMemorySize, ATT_SMEM);

    split16_kernel<<<(M_ * 512) / 256, 256>>>((const float2*)x, (__half2*)xc);
    wconv_kernel<<<(4 * 1024 * 512) / 256, 256>>>(
        (const float2*)d_in[3], (const float2*)d_in[4],
        (const float2*)d_in[5], (const float2*)d_in[6], (__half2*)wc);

    // Fused QKV projection + RoPE + v convert (grid 12 x 32)
    gemm_f16_kernel<<<dim3(12, M_ / 128), 256, GEMM_SMEM>>>(
        xc, wc, nullptr, qhp, khp, vhp, fc, fs, 0);

    // Flash attention -> split fp16 attn directly
    attn_hmma_kernel<<<dim3(16, 32), 256, ATT_SMEM>>>(qhp, khp, vhp, ac);

    // Output projection (grid 4 x 32)
    gemm_f16_kernel<<<dim3(4, M_ / 128), 256, GEMM_SMEM>>>(
        ac, wc + (size_t)3 * D_ * D_, out, nullptr, nullptr, nullptr,
        nullptr, nullptr, 1);
}